// round 1
// baseline (speedup 1.0000x reference)
#include <cuda_runtime.h>
#include <cuda_bf16.h>
#include <math.h>

// ---------------- problem constants ----------------
#define BATCH 2
#define SEQ   2048
#define DMODEL 1024
#define NHEADS 16
#define HDIM  64
#define ROWS  (BATCH*SEQ)          // 4096
#define WHALF 128                  // WINDOW/2
#define LN_EPS 1e-5f

// ---------------- scratch (device globals; no allocations allowed) ----------
__device__ float g_h   [ROWS * DMODEL];        // LN1(x)
__device__ float g_qkv [ROWS * 3 * DMODEL];    // qkv projection
__device__ float g_att [ROWS * DMODEL];        // attention output (pre out_w)
__device__ float g_x1  [ROWS * DMODEL];        // x + attn_out
__device__ float g_h2  [ROWS * DMODEL];        // LN2(x1)
__device__ float g_ffn [ROWS * 2 * DMODEL];    // gelu(h2 @ w1 + b1)

// ---------------- LayerNorm: one block per row, 256 threads -----------------
__global__ __launch_bounds__(256) void ln_kernel(
    const float* __restrict__ x, const float* __restrict__ g,
    const float* __restrict__ b, float* __restrict__ out)
{
    const int row = blockIdx.x;
    const float* xr = x + (size_t)row * DMODEL;
    float* orow = out + (size_t)row * DMODEL;
    const int tid = threadIdx.x;

    float v[4];
    float s = 0.f, ss = 0.f;
#pragma unroll
    for (int i = 0; i < 4; i++) {
        v[i] = xr[tid + i * 256];
        s += v[i];
        ss += v[i] * v[i];
    }
    // warp reduce
#pragma unroll
    for (int off = 16; off; off >>= 1) {
        s  += __shfl_xor_sync(0xffffffffu, s, off);
        ss += __shfl_xor_sync(0xffffffffu, ss, off);
    }
    __shared__ float rs[8], rss[8];
    const int warp = tid >> 5, lane = tid & 31;
    if (lane == 0) { rs[warp] = s; rss[warp] = ss; }
    __syncthreads();
    __shared__ float s_mu, s_inv;
    if (tid == 0) {
        float S = 0.f, SS = 0.f;
#pragma unroll
        for (int w = 0; w < 8; w++) { S += rs[w]; SS += rss[w]; }
        float mu = S * (1.0f / DMODEL);
        float var = SS * (1.0f / DMODEL) - mu * mu;
        s_mu = mu;
        s_inv = rsqrtf(var + LN_EPS);
    }
    __syncthreads();
    const float mu = s_mu, inv = s_inv;
#pragma unroll
    for (int i = 0; i < 4; i++) {
        int c = tid + i * 256;
        orow[c] = (v[i] - mu) * inv * g[c] + b[c];
    }
}

// ---------------- SGEMM: C = A[MxK] @ B[KxN] + bias, fused epilogue ---------
// EPI 0: +bias ; EPI 1: +bias+residual ; EPI 2: gelu(.+bias)
// Tile 128x128, BK=8, 256 threads, 8x8 per thread. M,N %128==0, K %8==0.
#define AS_STRIDE 132
#define BS_STRIDE 132

template<int EPI>
__global__ __launch_bounds__(256) void gemm_kernel(
    const float* __restrict__ A, const float* __restrict__ Bm,
    const float* __restrict__ bias, const float* __restrict__ res,
    float* __restrict__ C, int M, int N, int K)
{
    __shared__ float As[8 * AS_STRIDE];
    __shared__ float Bs[8 * BS_STRIDE];

    const int tid = threadIdx.x;
    const int m0 = blockIdx.y * 128;
    const int n0 = blockIdx.x * 128;
    const int tx = tid & 15, ty = tid >> 4;

    float acc[8][8];
#pragma unroll
    for (int i = 0; i < 8; i++)
#pragma unroll
        for (int j = 0; j < 8; j++) acc[i][j] = 0.f;

    // load indices
    const int ar = tid >> 1;          // 0..127 (A row within tile)
    const int as = tid & 1;           // 0..1   (which float4 of 8 k's)
    const int bk = tid >> 5;          // 0..7   (B k row)
    const int bc = (tid & 31) * 4;    // 0..124 (B col)

    for (int k0 = 0; k0 < K; k0 += 8) {
        __syncthreads();
        {
            float4 av = *(const float4*)(A + (size_t)(m0 + ar) * K + k0 + as * 4);
            As[(as * 4 + 0) * AS_STRIDE + ar] = av.x;
            As[(as * 4 + 1) * AS_STRIDE + ar] = av.y;
            As[(as * 4 + 2) * AS_STRIDE + ar] = av.z;
            As[(as * 4 + 3) * AS_STRIDE + ar] = av.w;
            float4 bv = *(const float4*)(Bm + (size_t)(k0 + bk) * N + n0 + bc);
            *(float4*)&Bs[bk * BS_STRIDE + bc] = bv;
        }
        __syncthreads();
#pragma unroll
        for (int k = 0; k < 8; k++) {
            float a[8], b[8];
            *(float4*)(a)     = *(const float4*)&As[k * AS_STRIDE + ty * 8];
            *(float4*)(a + 4) = *(const float4*)&As[k * AS_STRIDE + ty * 8 + 4];
            *(float4*)(b)     = *(const float4*)&Bs[k * BS_STRIDE + tx * 8];
            *(float4*)(b + 4) = *(const float4*)&Bs[k * BS_STRIDE + tx * 8 + 4];
#pragma unroll
            for (int i = 0; i < 8; i++)
#pragma unroll
                for (int j = 0; j < 8; j++)
                    acc[i][j] = fmaf(a[i], b[j], acc[i][j]);
        }
    }

#pragma unroll
    for (int i = 0; i < 8; i++) {
        const int row = m0 + ty * 8 + i;
#pragma unroll
        for (int j = 0; j < 8; j++) {
            const int col = n0 + tx * 8 + j;
            float v = acc[i][j] + bias[col];
            if (EPI == 1) v += res[(size_t)row * N + col];
            if (EPI == 2) v = 0.5f * v * (1.0f + erff(v * 0.70710678118654752f));
            C[(size_t)row * N + col] = v;
        }
    }
}

// ---------------- Windowed attention ----------------------------------------
// Block handles (b, h, 64 queries). Key span = [q0-128, q0+191] = 320 slots.
// smem: S[64][321] scores, Qs[64][65], KVs[64][65]  (~112.8 KB dynamic)
#define QT 64
#define KSPAN 320
#define SSTR 321
#define QKSTR 65
#define ATT_SMEM_FLOATS (QT*SSTR + QT*QKSTR + QT*QKSTR)

__global__ __launch_bounds__(256) void attn_kernel(
    const float* __restrict__ qkv, float* __restrict__ attn_out)
{
    const int q0 = blockIdx.x * QT;
    const int h  = blockIdx.y;
    const int b  = blockIdx.z;

    extern __shared__ float sm[];
    float* S   = sm;                    // QT * SSTR
    float* Qs  = S + QT * SSTR;         // QT * QKSTR
    float* KVs = Qs + QT * QKSTR;       // 64 * QKSTR

    const int tid = threadIdx.x;
    const int tx = tid & 15, ty = tid >> 4;
    const int kbase = q0 - WHALF;
    const float NEG_INF = __int_as_float(0xff800000);

    // load Q tile: Qs[qr][d]
    for (int idx = tid; idx < QT * 16; idx += 256) {
        int r = idx >> 4, seg = idx & 15;
        float4 v = *(const float4*)(qkv + ((size_t)(b * SEQ + q0 + r)) * 3 * DMODEL
                                    + h * HDIM + seg * 4);
        Qs[r * QKSTR + seg * 4 + 0] = v.x;
        Qs[r * QKSTR + seg * 4 + 1] = v.y;
        Qs[r * QKSTR + seg * 4 + 2] = v.z;
        Qs[r * QKSTR + seg * 4 + 3] = v.w;
    }

    // ---- pass A: scores ----
    for (int c = 0; c < 5; c++) {
        __syncthreads();   // (first iter also guards Qs writes)
        // load K chunk: KVs[j][d]
        for (int idx = tid; idx < 64 * 16; idx += 256) {
            int r = idx >> 4, seg = idx & 15;
            int kidx = kbase + c * 64 + r;
            float4 v = make_float4(0.f, 0.f, 0.f, 0.f);
            if (kidx >= 0 && kidx < SEQ)
                v = *(const float4*)(qkv + ((size_t)(b * SEQ + kidx)) * 3 * DMODEL
                                     + DMODEL + h * HDIM + seg * 4);
            KVs[r * QKSTR + seg * 4 + 0] = v.x;
            KVs[r * QKSTR + seg * 4 + 1] = v.y;
            KVs[r * QKSTR + seg * 4 + 2] = v.z;
            KVs[r * QKSTR + seg * 4 + 3] = v.w;
        }
        __syncthreads();

        float acc[4][4];
#pragma unroll
        for (int i = 0; i < 4; i++)
#pragma unroll
            for (int j = 0; j < 4; j++) acc[i][j] = 0.f;

#pragma unroll 8
        for (int d = 0; d < HDIM; d++) {
            float a[4], bb[4];
#pragma unroll
            for (int i = 0; i < 4; i++) a[i]  = Qs[(ty * 4 + i) * QKSTR + d];
#pragma unroll
            for (int j = 0; j < 4; j++) bb[j] = KVs[(tx * 4 + j) * QKSTR + d];
#pragma unroll
            for (int i = 0; i < 4; i++)
#pragma unroll
                for (int j = 0; j < 4; j++)
                    acc[i][j] = fmaf(a[i], bb[j], acc[i][j]);
        }

#pragma unroll
        for (int i = 0; i < 4; i++) {
            const int qr = ty * 4 + i;
#pragma unroll
            for (int j = 0; j < 4; j++) {
                const int kc = tx * 4 + j;
                const int rel = c * 64 + kc - qr;       // kidx - qidx + 128
                const int kidx = kbase + c * 64 + kc;
                bool ok = (rel >= 0) && (rel <= 2 * WHALF) && (kidx >= 0) && (kidx < SEQ);
                S[qr * SSTR + c * 64 + kc] = ok ? acc[i][j] * 0.125f : NEG_INF;
            }
        }
    }
    __syncthreads();

    // ---- softmax per row (warp per row, 8 rows per warp) ----
    {
        const int warp = tid >> 5, lane = tid & 31;
        for (int row = warp; row < QT; row += 8) {
            float* Sr = S + row * SSTR;
            float m = NEG_INF;
            for (int jj = lane; jj < KSPAN; jj += 32) m = fmaxf(m, Sr[jj]);
#pragma unroll
            for (int off = 16; off; off >>= 1)
                m = fmaxf(m, __shfl_xor_sync(0xffffffffu, m, off));
            float ssum = 0.f;
            for (int jj = lane; jj < KSPAN; jj += 32) {
                float e = expf(Sr[jj] - m);
                Sr[jj] = e;
                ssum += e;
            }
#pragma unroll
            for (int off = 16; off; off >>= 1)
                ssum += __shfl_xor_sync(0xffffffffu, ssum, off);
            float invs = 1.0f / ssum;
            for (int jj = lane; jj < KSPAN; jj += 32) Sr[jj] *= invs;
        }
    }

    // ---- pass B: out = P @ V ----
    float oacc[4][4];
#pragma unroll
    for (int i = 0; i < 4; i++)
#pragma unroll
        for (int j = 0; j < 4; j++) oacc[i][j] = 0.f;

    for (int c = 0; c < 5; c++) {
        __syncthreads();   // guard KVs reuse (also after softmax for c=0)
        for (int idx = tid; idx < 64 * 16; idx += 256) {
            int r = idx >> 4, seg = idx & 15;
            int kidx = kbase + c * 64 + r;
            float4 v = make_float4(0.f, 0.f, 0.f, 0.f);
            if (kidx >= 0 && kidx < SEQ)
                v = *(const float4*)(qkv + ((size_t)(b * SEQ + kidx)) * 3 * DMODEL
                                     + 2 * DMODEL + h * HDIM + seg * 4);
            KVs[r * QKSTR + seg * 4 + 0] = v.x;
            KVs[r * QKSTR + seg * 4 + 1] = v.y;
            KVs[r * QKSTR + seg * 4 + 2] = v.z;
            KVs[r * QKSTR + seg * 4 + 3] = v.w;
        }
        __syncthreads();

#pragma unroll 8
        for (int j = 0; j < 64; j++) {
            float a[4], bb[4];
#pragma unroll
            for (int i = 0; i < 4; i++)  a[i]  = S[(ty * 4 + i) * SSTR + c * 64 + j];
#pragma unroll
            for (int jj = 0; jj < 4; jj++) bb[jj] = KVs[j * QKSTR + tx * 4 + jj];
#pragma unroll
            for (int i = 0; i < 4; i++)
#pragma unroll
                for (int jj = 0; jj < 4; jj++)
                    oacc[i][jj] = fmaf(a[i], bb[jj], oacc[i][jj]);
        }
    }

    // write: attn buffer is [B, L, H*hd]
#pragma unroll
    for (int i = 0; i < 4; i++) {
        const int qr = ty * 4 + i;
#pragma unroll
        for (int j = 0; j < 4; j++) {
            const int d = tx * 4 + j;
            attn_out[((size_t)(b * SEQ + q0 + qr)) * DMODEL + h * HDIM + d] = oacc[i][j];
        }
    }
}

// ---------------- launch -----------------------------------------------------
extern "C" void kernel_launch(void* const* d_in, const int* in_sizes, int n_in,
                              void* d_out, int out_size)
{
    const float* x      = (const float*)d_in[0];
    const float* qkv_w  = (const float*)d_in[1];
    const float* qkv_b  = (const float*)d_in[2];
    const float* out_w  = (const float*)d_in[3];
    const float* out_b  = (const float*)d_in[4];
    const float* ln1_g  = (const float*)d_in[5];
    const float* ln1_b  = (const float*)d_in[6];
    const float* ln2_g  = (const float*)d_in[7];
    const float* ln2_b  = (const float*)d_in[8];
    const float* ffn_w1 = (const float*)d_in[9];
    const float* ffn_b1 = (const float*)d_in[10];
    const float* ffn_w2 = (const float*)d_in[11];
    const float* ffn_b2 = (const float*)d_in[12];
    float* out = (float*)d_out;

    float *h, *qkv, *att, *x1, *h2, *ffn;
    cudaGetSymbolAddress((void**)&h,   g_h);
    cudaGetSymbolAddress((void**)&qkv, g_qkv);
    cudaGetSymbolAddress((void**)&att, g_att);
    cudaGetSymbolAddress((void**)&x1,  g_x1);
    cudaGetSymbolAddress((void**)&h2,  g_h2);
    cudaGetSymbolAddress((void**)&ffn, g_ffn);

    const size_t att_smem = (size_t)ATT_SMEM_FLOATS * sizeof(float);
    cudaFuncSetAttribute(attn_kernel, cudaFuncAttributeMaxDynamicSharedMemorySize,
                         (int)att_smem);

    // 1) h = LN1(x)
    ln_kernel<<<ROWS, 256>>>(x, ln1_g, ln1_b, h);
    // 2) qkv = h @ qkv_w + qkv_b         [4096 x 3072]
    gemm_kernel<0><<<dim3(3 * DMODEL / 128, ROWS / 128), 256>>>(
        h, qkv_w, qkv_b, nullptr, qkv, ROWS, 3 * DMODEL, DMODEL);
    // 3) windowed attention -> att        [4096 x 1024]
    attn_kernel<<<dim3(SEQ / QT, NHEADS, BATCH), 256, att_smem>>>(qkv, att);
    // 4) x1 = x + att @ out_w + out_b
    gemm_kernel<1><<<dim3(DMODEL / 128, ROWS / 128), 256>>>(
        att, out_w, out_b, x, x1, ROWS, DMODEL, DMODEL);
    // 5) h2 = LN2(x1)
    ln_kernel<<<ROWS, 256>>>(x1, ln2_g, ln2_b, h2);
    // 6) ffn = gelu(h2 @ ffn_w1 + ffn_b1) [4096 x 2048]
    gemm_kernel<2><<<dim3(2 * DMODEL / 128, ROWS / 128), 256>>>(
        h2, ffn_w1, ffn_b1, nullptr, ffn, ROWS, 2 * DMODEL, DMODEL);
    // 7) out = x1 + ffn @ ffn_w2 + ffn_b2
    gemm_kernel<1><<<dim3(DMODEL / 128, ROWS / 128), 256>>>(
        ffn, ffn_w2, ffn_b2, x1, out, ROWS, DMODEL, 2 * DMODEL);
}

// round 3
// speedup vs baseline: 1.9459x; 1.9459x over previous
#include <cuda_runtime.h>
#include <cuda_bf16.h>
#include <math.h>
#include <stdint.h>

// ---------------- problem constants ----------------
#define BATCH 2
#define SEQ   2048
#define DMODEL 1024
#define NHEADS 16
#define HDIM  64
#define ROWS  (BATCH*SEQ)          // 4096
#define WHALF 128
#define LN_EPS 1e-5f

// ---------------- scratch (device globals) ----------
__device__ float g_qkv [ROWS * 3 * DMODEL];    // f32 (attention consumes)
__device__ float g_x1  [ROWS * DMODEL];        // f32 (residual + LN2 input)

// bf16 hi/lo split activations (GEMM A operands)
__device__ __nv_bfloat16 g_h_h  [ROWS * DMODEL],     g_h_l  [ROWS * DMODEL];
__device__ __nv_bfloat16 g_att_h[ROWS * DMODEL],     g_att_l[ROWS * DMODEL];
__device__ __nv_bfloat16 g_h2_h [ROWS * DMODEL],     g_h2_l [ROWS * DMODEL];
__device__ __nv_bfloat16 g_ffn_h[ROWS * 2 * DMODEL], g_ffn_l[ROWS * 2 * DMODEL];

// transposed + bf16-split weights: [N, K] row-major
__device__ __nv_bfloat16 g_wqkv_h[3*DMODEL*DMODEL], g_wqkv_l[3*DMODEL*DMODEL];
__device__ __nv_bfloat16 g_wout_h[DMODEL*DMODEL],   g_wout_l[DMODEL*DMODEL];
__device__ __nv_bfloat16 g_wf1_h [2*DMODEL*DMODEL], g_wf1_l [2*DMODEL*DMODEL];
__device__ __nv_bfloat16 g_wf2_h [2*DMODEL*DMODEL], g_wf2_l [2*DMODEL*DMODEL];

// ---------------- helpers ----------------------------------------------------
__device__ __forceinline__ uint32_t smem_u32(const void* p) {
    uint32_t a;
    asm("{ .reg .u64 t; cvta.to.shared.u64 t, %1; cvt.u32.u64 %0, t; }"
        : "=r"(a) : "l"(p));
    return a;
}
#define SW128(off) ((off) ^ (((off) >> 3) & 0x70))

__device__ __forceinline__ void cp16(uint32_t smem, const void* g) {
    asm volatile("cp.async.cg.shared.global [%0], [%1], 16;"
        :: "r"(smem), "l"(g) : "memory");
}
#define CP_COMMIT() asm volatile("cp.async.commit_group;" ::: "memory")
#define CP_WAIT(n)  asm volatile("cp.async.wait_group %0;" :: "n"(n) : "memory")

#define LDSM_X4(r0,r1,r2,r3,addr) \
    asm volatile("ldmatrix.sync.aligned.m8n8.x4.shared.b16 {%0,%1,%2,%3}, [%4];" \
        : "=r"(r0), "=r"(r1), "=r"(r2), "=r"(r3) : "r"(addr))
#define LDSM_X2(r0,r1,addr) \
    asm volatile("ldmatrix.sync.aligned.m8n8.x2.shared.b16 {%0,%1}, [%2];" \
        : "=r"(r0), "=r"(r1) : "r"(addr))

__device__ __forceinline__ void mma16816(float* d, const uint32_t* a, const uint32_t* b) {
    asm volatile(
        "mma.sync.aligned.m16n8k16.row.col.f32.bf16.bf16.f32 "
        "{%0,%1,%2,%3}, {%4,%5,%6,%7}, {%8,%9}, {%0,%1,%2,%3};"
        : "+f"(d[0]), "+f"(d[1]), "+f"(d[2]), "+f"(d[3])
        : "r"(a[0]), "r"(a[1]), "r"(a[2]), "r"(a[3]), "r"(b[0]), "r"(b[1]));
}

// ---------------- transpose + bf16-split weights -----------------------------
// w [K,N] f32 -> th/tl [N,K] bf16
__global__ __launch_bounds__(256) void transpose_split(
    const float* __restrict__ w, __nv_bfloat16* __restrict__ th,
    __nv_bfloat16* __restrict__ tl, int K, int N)
{
    __shared__ float t[32][33];
    const int n0 = blockIdx.x * 32, k0 = blockIdx.y * 32;
    const int c = threadIdx.x & 31, r = threadIdx.x >> 5;
#pragma unroll
    for (int i = 0; i < 32; i += 8)
        t[r + i][c] = w[(size_t)(k0 + r + i) * N + n0 + c];
    __syncthreads();
#pragma unroll
    for (int i = 0; i < 32; i += 8) {
        float v = t[c][r + i];
        __nv_bfloat16 hb = __float2bfloat16_rn(v);
        float lo = v - __bfloat162float(hb);
        size_t o = (size_t)(n0 + r + i) * K + k0 + c;
        th[o] = hb;
        tl[o] = __float2bfloat16_rn(lo);
    }
}

// ---------------- HMMA GEMM --------------------------------------------------
// C[M,N] = A[M,K] @ B^T, A/B pre-split bf16 hi/lo [rows, K].
// 128x128 CTA tile, 8 warps of 64x32, K-step 64, 2-stage cp.async pipeline.
// EPI 0: f32 = acc+bias ; 1: f32 = acc+bias+res ; 2: split bf16 = gelu(acc+bias)
#define OFF_AH 0
#define OFF_AL 16384
#define OFF_BH 32768
#define OFF_BL 49152
#define STAGE_BYTES 65536
#define GEMM_SMEM (2*STAGE_BYTES)

template<int EPI>
__global__ __launch_bounds__(256, 1) void hmma_gemm(
    const __nv_bfloat16* __restrict__ Ah, const __nv_bfloat16* __restrict__ Al,
    const __nv_bfloat16* __restrict__ Bh, const __nv_bfloat16* __restrict__ Bl,
    const float* __restrict__ bias, const float* __restrict__ res,
    float* __restrict__ Cf, __nv_bfloat16* __restrict__ Ch,
    __nv_bfloat16* __restrict__ Cl, int M, int N, int K)
{
    extern __shared__ char smc[];
    const uint32_t sbase = smem_u32(smc);
    const int tid = threadIdx.x, wid = tid >> 5, lane = tid & 31;
    const int m0 = blockIdx.y * 128, n0 = blockIdx.x * 128;
    const int mw = (wid >> 2) * 64;   // warp m offset in tile
    const int nw = (wid & 3) * 32;    // warp n offset in tile

    float acc[4][4][4];
#pragma unroll
    for (int i = 0; i < 4; i++)
#pragma unroll
        for (int j = 0; j < 4; j++)
#pragma unroll
            for (int r = 0; r < 4; r++) acc[i][j][r] = 0.f;

    const int S = K >> 6;
    const int lrow = tid >> 1;        // 0..127 loader row
    const int lsq  = (tid & 1) * 4;   // loader seg start

    auto load_stage = [&](int buf, int koff) {
        const uint32_t st = sbase + buf * STAGE_BYTES;
        const __nv_bfloat16* gAh = Ah + (size_t)(m0 + lrow) * K + koff;
        const __nv_bfloat16* gAl = Al + (size_t)(m0 + lrow) * K + koff;
        const __nv_bfloat16* gBh = Bh + (size_t)(n0 + lrow) * K + koff;
        const __nv_bfloat16* gBl = Bl + (size_t)(n0 + lrow) * K + koff;
#pragma unroll
        for (int j = 0; j < 4; j++) {
            const int seg = lsq + j;
            const uint32_t so = SW128((uint32_t)(lrow * 128 + seg * 16));
            cp16(st + OFF_AH + so, gAh + seg * 8);
            cp16(st + OFF_AL + so, gAl + seg * 8);
            cp16(st + OFF_BH + so, gBh + seg * 8);
            cp16(st + OFF_BL + so, gBl + seg * 8);
        }
        CP_COMMIT();
    };

    // per-thread ldmatrix address components
    const int a_r  = mw + (lane & 15);            // + i*16
    const int a_k  = (lane >> 4) << 3;            // + kk*16
    const int b_r  = nw + (lane & 7);             // + j*8
    const int b_k  = lane & 8;                    // + kk*16

    load_stage(0, 0);

    for (int s = 0; s < S; s++) {
        const int buf = s & 1;
        if (s + 1 < S) { load_stage(buf ^ 1, (s + 1) << 6); CP_WAIT(1); }
        else           { CP_WAIT(0); }
        __syncthreads();

        const uint32_t st = sbase + buf * STAGE_BYTES;
#pragma unroll
        for (int kk = 0; kk < 4; kk++) {
            uint32_t ah[4][4], bh[4][2], bl[4][2];
#pragma unroll
            for (int i = 0; i < 4; i++) {
                uint32_t ad = st + OFF_AH +
                    SW128((uint32_t)((a_r + i * 16) * 128 + (kk * 16 + a_k) * 2));
                LDSM_X4(ah[i][0], ah[i][1], ah[i][2], ah[i][3], ad);
            }
#pragma unroll
            for (int j = 0; j < 4; j++) {
                uint32_t off = SW128((uint32_t)((b_r + j * 8) * 128 + (kk * 16 + b_k) * 2));
                LDSM_X2(bh[j][0], bh[j][1], st + OFF_BH + off);
                LDSM_X2(bl[j][0], bl[j][1], st + OFF_BL + off);
            }
#pragma unroll
            for (int i = 0; i < 4; i++)
#pragma unroll
                for (int j = 0; j < 4; j++)
                    mma16816(acc[i][j], ah[i], bh[j]);
#pragma unroll
            for (int i = 0; i < 4; i++)
#pragma unroll
                for (int j = 0; j < 4; j++)
                    mma16816(acc[i][j], ah[i], bl[j]);
            // A-lo term (reuse ah regs)
#pragma unroll
            for (int i = 0; i < 4; i++) {
                uint32_t ad = st + OFF_AL +
                    SW128((uint32_t)((a_r + i * 16) * 128 + (kk * 16 + a_k) * 2));
                LDSM_X4(ah[i][0], ah[i][1], ah[i][2], ah[i][3], ad);
            }
#pragma unroll
            for (int i = 0; i < 4; i++)
#pragma unroll
                for (int j = 0; j < 4; j++)
                    mma16816(acc[i][j], ah[i], bh[j]);
        }
        __syncthreads();
    }

    // ---------------- epilogue ----------------
    const int er = lane >> 2;           // 0..7
    const int ec = 2 * (lane & 3);      // 0,2,4,6
#pragma unroll
    for (int i = 0; i < 4; i++) {
        const int row0 = m0 + mw + i * 16 + er;
        const int row1 = row0 + 8;
#pragma unroll
        for (int j = 0; j < 4; j++) {
            const int col = n0 + nw + j * 8 + ec;
            const float b0 = bias[col], b1 = bias[col + 1];
            float v0 = acc[i][j][0] + b0;
            float v1 = acc[i][j][1] + b1;
            float v2 = acc[i][j][2] + b0;
            float v3 = acc[i][j][3] + b1;
            if (EPI == 1) {
                const float2 r0 = *(const float2*)(res + (size_t)row0 * N + col);
                const float2 r1 = *(const float2*)(res + (size_t)row1 * N + col);
                v0 += r0.x; v1 += r0.y; v2 += r1.x; v3 += r1.y;
            }
            if (EPI == 2) {
                v0 = 0.5f * v0 * (1.0f + erff(v0 * 0.70710678118654752f));
                v1 = 0.5f * v1 * (1.0f + erff(v1 * 0.70710678118654752f));
                v2 = 0.5f * v2 * (1.0f + erff(v2 * 0.70710678118654752f));
                v3 = 0.5f * v3 * (1.0f + erff(v3 * 0.70710678118654752f));
                __nv_bfloat162 h0 = __floats2bfloat162_rn(v0, v1);
                __nv_bfloat162 h1 = __floats2bfloat162_rn(v2, v3);
                __nv_bfloat162 l0 = __floats2bfloat162_rn(
                    v0 - __low2float(h0), v1 - __high2float(h0));
                __nv_bfloat162 l1 = __floats2bfloat162_rn(
                    v2 - __low2float(h1), v3 - __high2float(h1));
                *(__nv_bfloat162*)(Ch + (size_t)row0 * N + col) = h0;
                *(__nv_bfloat162*)(Cl + (size_t)row0 * N + col) = l0;
                *(__nv_bfloat162*)(Ch + (size_t)row1 * N + col) = h1;
                *(__nv_bfloat162*)(Cl + (size_t)row1 * N + col) = l1;
            } else {
                *(float2*)(Cf + (size_t)row0 * N + col) = make_float2(v0, v1);
                *(float2*)(Cf + (size_t)row1 * N + col) = make_float2(v2, v3);
            }
        }
    }
}

// ---------------- LayerNorm (writes bf16 hi/lo split) ------------------------
__global__ __launch_bounds__(256) void ln_kernel(
    const float* __restrict__ x, const float* __restrict__ g,
    const float* __restrict__ b, __nv_bfloat16* __restrict__ oh,
    __nv_bfloat16* __restrict__ ol)
{
    const int row = blockIdx.x;
    const float* xr = x + (size_t)row * DMODEL;
    const int tid = threadIdx.x;

    float v[4];
    float s = 0.f, ss = 0.f;
#pragma unroll
    for (int i = 0; i < 4; i++) {
        v[i] = xr[tid + i * 256];
        s += v[i];
        ss += v[i] * v[i];
    }
#pragma unroll
    for (int off = 16; off; off >>= 1) {
        s  += __shfl_xor_sync(0xffffffffu, s, off);
        ss += __shfl_xor_sync(0xffffffffu, ss, off);
    }
    __shared__ float rs[8], rss[8];
    const int warp = tid >> 5, lane = tid & 31;
    if (lane == 0) { rs[warp] = s; rss[warp] = ss; }
    __syncthreads();
    __shared__ float s_mu, s_inv;
    if (tid == 0) {
        float S = 0.f, SS = 0.f;
#pragma unroll
        for (int w = 0; w < 8; w++) { S += rs[w]; SS += rss[w]; }
        float mu = S * (1.0f / DMODEL);
        float var = SS * (1.0f / DMODEL) - mu * mu;
        s_mu = mu;
        s_inv = rsqrtf(var + LN_EPS);
    }
    __syncthreads();
    const float mu = s_mu, inv = s_inv;
#pragma unroll
    for (int i = 0; i < 4; i++) {
        int c = tid + i * 256;
        float o = (v[i] - mu) * inv * g[c] + b[c];
        __nv_bfloat16 hb = __float2bfloat16_rn(o);
        oh[(size_t)row * DMODEL + c] = hb;
        ol[(size_t)row * DMODEL + c] = __float2bfloat16_rn(o - __bfloat162float(hb));
    }
}

// ---------------- Windowed attention (writes bf16 hi/lo split) ---------------
#define QT 64
#define KSPAN 320
#define SSTR 321
#define QKSTR 65
#define ATT_SMEM_FLOATS (QT*SSTR + QT*QKSTR + QT*QKSTR)

__global__ __launch_bounds__(256) void attn_kernel(
    const float* __restrict__ qkv, __nv_bfloat16* __restrict__ ath,
    __nv_bfloat16* __restrict__ atl)
{
    const int q0 = blockIdx.x * QT;
    const int h  = blockIdx.y;
    const int b  = blockIdx.z;

    extern __shared__ float smf[];
    float* S   = smf;
    float* Qs  = S + QT * SSTR;
    float* KVs = Qs + QT * QKSTR;

    const int tid = threadIdx.x;
    const int tx = tid & 15, ty = tid >> 4;
    const int kbase = q0 - WHALF;
    const float NEG_INF = __int_as_float(0xff800000);

    for (int idx = tid; idx < QT * 16; idx += 256) {
        int r = idx >> 4, seg = idx & 15;
        float4 v = *(const float4*)(qkv + ((size_t)(b * SEQ + q0 + r)) * 3 * DMODEL
                                    + h * HDIM + seg * 4);
        Qs[r * QKSTR + seg * 4 + 0] = v.x;
        Qs[r * QKSTR + seg * 4 + 1] = v.y;
        Qs[r * QKSTR + seg * 4 + 2] = v.z;
        Qs[r * QKSTR + seg * 4 + 3] = v.w;
    }

    for (int c = 0; c < 5; c++) {
        __syncthreads();
        for (int idx = tid; idx < 64 * 16; idx += 256) {
            int r = idx >> 4, seg = idx & 15;
            int kidx = kbase + c * 64 + r;
            float4 v = make_float4(0.f, 0.f, 0.f, 0.f);
            if (kidx >= 0 && kidx < SEQ)
                v = *(const float4*)(qkv + ((size_t)(b * SEQ + kidx)) * 3 * DMODEL
                                     + DMODEL + h * HDIM + seg * 4);
            KVs[r * QKSTR + seg * 4 + 0] = v.x;
            KVs[r * QKSTR + seg * 4 + 1] = v.y;
            KVs[r * QKSTR + seg * 4 + 2] = v.z;
            KVs[r * QKSTR + seg * 4 + 3] = v.w;
        }
        __syncthreads();

        float acc[4][4];
#pragma unroll
        for (int i = 0; i < 4; i++)
#pragma unroll
            for (int j = 0; j < 4; j++) acc[i][j] = 0.f;

#pragma unroll 8
        for (int d = 0; d < HDIM; d++) {
            float a[4], bb[4];
#pragma unroll
            for (int i = 0; i < 4; i++) a[i]  = Qs[(ty * 4 + i) * QKSTR + d];
#pragma unroll
            for (int j = 0; j < 4; j++) bb[j] = KVs[(tx * 4 + j) * QKSTR + d];
#pragma unroll
            for (int i = 0; i < 4; i++)
#pragma unroll
                for (int j = 0; j < 4; j++)
                    acc[i][j] = fmaf(a[i], bb[j], acc[i][j]);
        }

#pragma unroll
        for (int i = 0; i < 4; i++) {
            const int qr = ty * 4 + i;
#pragma unroll
            for (int j = 0; j < 4; j++) {
                const int kc = tx * 4 + j;
                const int rel = c * 64 + kc - qr;
                const int kidx = kbase + c * 64 + kc;
                bool ok = (rel >= 0) && (rel <= 2 * WHALF) && (kidx >= 0) && (kidx < SEQ);
                S[qr * SSTR + c * 64 + kc] = ok ? acc[i][j] * 0.125f : NEG_INF;
            }
        }
    }
    __syncthreads();

    {
        const int warp = tid >> 5, lane = tid & 31;
        for (int row = warp; row < QT; row += 8) {
            float* Sr = S + row * SSTR;
            float m = NEG_INF;
            for (int jj = lane; jj < KSPAN; jj += 32) m = fmaxf(m, Sr[jj]);
#pragma unroll
            for (int off = 16; off; off >>= 1)
                m = fmaxf(m, __shfl_xor_sync(0xffffffffu, m, off));
            float ssum = 0.f;
            for (int jj = lane; jj < KSPAN; jj += 32) {
                float e = expf(Sr[jj] - m);
                Sr[jj] = e;
                ssum += e;
            }
#pragma unroll
            for (int off = 16; off; off >>= 1)
                ssum += __shfl_xor_sync(0xffffffffu, ssum, off);
            float invs = 1.0f / ssum;
            for (int jj = lane; jj < KSPAN; jj += 32) Sr[jj] *= invs;
        }
    }

    float oacc[4][4];
#pragma unroll
    for (int i = 0; i < 4; i++)
#pragma unroll
        for (int j = 0; j < 4; j++) oacc[i][j] = 0.f;

    for (int c = 0; c < 5; c++) {
        __syncthreads();
        for (int idx = tid; idx < 64 * 16; idx += 256) {
            int r = idx >> 4, seg = idx & 15;
            int kidx = kbase + c * 64 + r;
            float4 v = make_float4(0.f, 0.f, 0.f, 0.f);
            if (kidx >= 0 && kidx < SEQ)
                v = *(const float4*)(qkv + ((size_t)(b * SEQ + kidx)) * 3 * DMODEL
                                     + 2 * DMODEL + h * HDIM + seg * 4);
            KVs[r * QKSTR + seg * 4 + 0] = v.x;
            KVs[r * QKSTR + seg * 4 + 1] = v.y;
            KVs[r * QKSTR + seg * 4 + 2] = v.z;
            KVs[r * QKSTR + seg * 4 + 3] = v.w;
        }
        __syncthreads();

#pragma unroll 8
        for (int j = 0; j < 64; j++) {
            float a[4], bb[4];
#pragma unroll
            for (int i = 0; i < 4; i++)  a[i]  = S[(ty * 4 + i) * SSTR + c * 64 + j];
#pragma unroll
            for (int jj = 0; jj < 4; jj++) bb[jj] = KVs[j * QKSTR + tx * 4 + jj];
#pragma unroll
            for (int i = 0; i < 4; i++)
#pragma unroll
                for (int jj = 0; jj < 4; jj++)
                    oacc[i][jj] = fmaf(a[i], bb[jj], oacc[i][jj]);
        }
    }

#pragma unroll
    for (int i = 0; i < 4; i++) {
        const int qr = ty * 4 + i;
#pragma unroll
        for (int j = 0; j < 4; j++) {
            const int d = tx * 4 + j;
            float v = oacc[i][j];
            __nv_bfloat16 hb = __float2bfloat16_rn(v);
            size_t off = ((size_t)(b * SEQ + q0 + qr)) * DMODEL + h * HDIM + d;
            ath[off] = hb;
            atl[off] = __float2bfloat16_rn(v - __bfloat162float(hb));
        }
    }
}

// ---------------- launch -----------------------------------------------------
extern "C" void kernel_launch(void* const* d_in, const int* in_sizes, int n_in,
                              void* d_out, int out_size)
{
    const float* x      = (const float*)d_in[0];
    const float* qkv_w  = (const float*)d_in[1];
    const float* qkv_b  = (const float*)d_in[2];
    const float* out_w  = (const float*)d_in[3];
    const float* out_b  = (const float*)d_in[4];
    const float* ln1_g  = (const float*)d_in[5];
    const float* ln1_b  = (const float*)d_in[6];
    const float* ln2_g  = (const float*)d_in[7];
    const float* ln2_b  = (const float*)d_in[8];
    const float* ffn_w1 = (const float*)d_in[9];
    const float* ffn_b1 = (const float*)d_in[10];
    const float* ffn_w2 = (const float*)d_in[11];
    const float* ffn_b2 = (const float*)d_in[12];
    float* out = (float*)d_out;

    float *qkv, *x1;
    cudaGetSymbolAddress((void**)&qkv, g_qkv);
    cudaGetSymbolAddress((void**)&x1,  g_x1);

    __nv_bfloat16 *hh, *hl, *atth, *attl, *h2h, *h2l, *ffh, *ffl;
    cudaGetSymbolAddress((void**)&hh,   g_h_h);
    cudaGetSymbolAddress((void**)&hl,   g_h_l);
    cudaGetSymbolAddress((void**)&atth, g_att_h);
    cudaGetSymbolAddress((void**)&attl, g_att_l);
    cudaGetSymbolAddress((void**)&h2h,  g_h2_h);
    cudaGetSymbolAddress((void**)&h2l,  g_h2_l);
    cudaGetSymbolAddress((void**)&ffh,  g_ffn_h);
    cudaGetSymbolAddress((void**)&ffl,  g_ffn_l);

    __nv_bfloat16 *wqh, *wql, *woh, *wol, *w1h, *w1l, *w2h, *w2l;
    cudaGetSymbolAddress((void**)&wqh, g_wqkv_h);
    cudaGetSymbolAddress((void**)&wql, g_wqkv_l);
    cudaGetSymbolAddress((void**)&woh, g_wout_h);
    cudaGetSymbolAddress((void**)&wol, g_wout_l);
    cudaGetSymbolAddress((void**)&w1h, g_wf1_h);
    cudaGetSymbolAddress((void**)&w1l, g_wf1_l);
    cudaGetSymbolAddress((void**)&w2h, g_wf2_h);
    cudaGetSymbolAddress((void**)&w2l, g_wf2_l);

    const size_t att_smem = (size_t)ATT_SMEM_FLOATS * sizeof(float);
    cudaFuncSetAttribute(attn_kernel, cudaFuncAttributeMaxDynamicSharedMemorySize,
                         (int)att_smem);
    cudaFuncSetAttribute(hmma_gemm<0>, cudaFuncAttributeMaxDynamicSharedMemorySize, GEMM_SMEM);
    cudaFuncSetAttribute(hmma_gemm<1>, cudaFuncAttributeMaxDynamicSharedMemorySize, GEMM_SMEM);
    cudaFuncSetAttribute(hmma_gemm<2>, cudaFuncAttributeMaxDynamicSharedMemorySize, GEMM_SMEM);

    // 0) weight transpose + split
    transpose_split<<<dim3(3*DMODEL/32, DMODEL/32), 256>>>(qkv_w, wqh, wql, DMODEL, 3*DMODEL);
    transpose_split<<<dim3(DMODEL/32,   DMODEL/32), 256>>>(out_w, woh, wol, DMODEL, DMODEL);
    transpose_split<<<dim3(2*DMODEL/32, DMODEL/32), 256>>>(ffn_w1, w1h, w1l, DMODEL, 2*DMODEL);
    transpose_split<<<dim3(DMODEL/32, 2*DMODEL/32), 256>>>(ffn_w2, w2h, w2l, 2*DMODEL, DMODEL);

    // 1) LN1(x) -> h hi/lo
    ln_kernel<<<ROWS, 256>>>(x, ln1_g, ln1_b, hh, hl);
    // 2) qkv = h @ qkv_w + qkv_b  (f32)
    hmma_gemm<0><<<dim3(3*DMODEL/128, ROWS/128), 256, GEMM_SMEM>>>(
        hh, hl, wqh, wql, qkv_b, nullptr, qkv, nullptr, nullptr,
        ROWS, 3*DMODEL, DMODEL);
    // 3) windowed attention -> att hi/lo
    attn_kernel<<<dim3(SEQ/QT, NHEADS, BATCH), 256, att_smem>>>(qkv, atth, attl);
    // 4) x1 = x + att @ out_w + out_b (f32)
    hmma_gemm<1><<<dim3(DMODEL/128, ROWS/128), 256, GEMM_SMEM>>>(
        atth, attl, woh, wol, out_b, x, x1, nullptr, nullptr,
        ROWS, DMODEL, DMODEL);
    // 5) LN2(x1) -> h2 hi/lo
    ln_kernel<<<ROWS, 256>>>(x1, ln2_g, ln2_b, h2h, h2l);
    // 6) ffn = gelu(h2 @ ffn_w1 + ffn_b1)  (split bf16)
    hmma_gemm<2><<<dim3(2*DMODEL/128, ROWS/128), 256, GEMM_SMEM>>>(
        h2h, h2l, w1h, w1l, ffn_b1, nullptr, nullptr, ffh, ffl,
        ROWS, 2*DMODEL, DMODEL);
    // 7) out = x1 + ffn @ ffn_w2 + ffn_b2 (f32)
    hmma_gemm<1><<<dim3(DMODEL/128, ROWS/128), 256, GEMM_SMEM>>>(
        ffh, ffl, w2h, w2l, ffn_b2, x1, out, nullptr, nullptr,
        ROWS, DMODEL, 2*DMODEL);
}

// round 4
// speedup vs baseline: 2.4872x; 1.2782x over previous
#include <cuda_runtime.h>
#include <cuda_fp16.h>
#include <cuda_bf16.h>
#include <math.h>
#include <stdint.h>

// ---------------- problem constants ----------------
#define BATCH 2
#define SEQ   2048
#define DMODEL 1024
#define NHEADS 16
#define HDIM  64
#define ROWS  (BATCH*SEQ)          // 4096
#define WHALF 128
#define LN_EPS 1e-5f

// ---------------- scratch (device globals) ----------
__device__ float g_qkv [ROWS * 3 * DMODEL];    // f32 (attention consumes)
__device__ float g_x1  [ROWS * DMODEL];        // f32 (residual + LN2 input)

// fp16 hi/lo split activations (GEMM A operands)
__device__ __half g_h_h  [ROWS * DMODEL],     g_h_l  [ROWS * DMODEL];
__device__ __half g_att_h[ROWS * DMODEL],     g_att_l[ROWS * DMODEL];
__device__ __half g_h2_h [ROWS * DMODEL],     g_h2_l [ROWS * DMODEL];
__device__ __half g_ffn_h[ROWS * 2 * DMODEL], g_ffn_l[ROWS * 2 * DMODEL];

// transposed fp16 weights: [N, K] row-major (hi only)
__device__ __half g_wqkv[3*DMODEL*DMODEL];
__device__ __half g_wout[DMODEL*DMODEL];
__device__ __half g_wf1 [2*DMODEL*DMODEL];
__device__ __half g_wf2 [2*DMODEL*DMODEL];

// ---------------- helpers ----------------------------------------------------
__device__ __forceinline__ uint32_t smem_u32(const void* p) {
    uint32_t a;
    asm("{ .reg .u64 t; cvta.to.shared.u64 t, %1; cvt.u32.u64 %0, t; }"
        : "=r"(a) : "l"(p));
    return a;
}
#define SW128(off) ((off) ^ (((off) >> 3) & 0x70))

__device__ __forceinline__ void cp16(uint32_t smem, const void* g) {
    asm volatile("cp.async.cg.shared.global [%0], [%1], 16;"
        :: "r"(smem), "l"(g) : "memory");
}
#define CP_COMMIT() asm volatile("cp.async.commit_group;" ::: "memory")
#define CP_WAIT(n)  asm volatile("cp.async.wait_group %0;" :: "n"(n) : "memory")

#define LDSM_X4(r0,r1,r2,r3,addr) \
    asm volatile("ldmatrix.sync.aligned.m8n8.x4.shared.b16 {%0,%1,%2,%3}, [%4];" \
        : "=r"(r0), "=r"(r1), "=r"(r2), "=r"(r3) : "r"(addr))
#define LDSM_X2(r0,r1,addr) \
    asm volatile("ldmatrix.sync.aligned.m8n8.x2.shared.b16 {%0,%1}, [%2];" \
        : "=r"(r0), "=r"(r1) : "r"(addr))

__device__ __forceinline__ void mma16816(float* d, const uint32_t* a, const uint32_t* b) {
    asm volatile(
        "mma.sync.aligned.m16n8k16.row.col.f32.f16.f16.f32 "
        "{%0,%1,%2,%3}, {%4,%5,%6,%7}, {%8,%9}, {%0,%1,%2,%3};"
        : "+f"(d[0]), "+f"(d[1]), "+f"(d[2]), "+f"(d[3])
        : "r"(a[0]), "r"(a[1]), "r"(a[2]), "r"(a[3]), "r"(b[0]), "r"(b[1]));
}

// ---------------- transpose weights: w [K,N] f32 -> t [N,K] fp16 -------------
__global__ __launch_bounds__(256) void transpose_fp16(
    const float* __restrict__ w, __half* __restrict__ t, int K, int N)
{
    __shared__ float tb[32][33];
    const int n0 = blockIdx.x * 32, k0 = blockIdx.y * 32;
    const int c = threadIdx.x & 31, r = threadIdx.x >> 5;
#pragma unroll
    for (int i = 0; i < 32; i += 8)
        tb[r + i][c] = w[(size_t)(k0 + r + i) * N + n0 + c];
    __syncthreads();
#pragma unroll
    for (int i = 0; i < 32; i += 8)
        t[(size_t)(n0 + r + i) * K + k0 + c] = __float2half_rn(tb[c][r + i]);
}

// ---------------- HMMA GEMM --------------------------------------------------
// C[M,N] = A[M,K] @ B^T ; A fp16 hi/lo split [M,K], B fp16 [N,K].
// 2 MMA terms: Ah*B + Al*B. 128x128 CTA tile, 8 warps of 64x32, K-step 64.
// 4-stage cp.async pipeline, single syncthreads per stage.
// EPI 0: f32 = acc+bias ; 1: f32 = acc+bias+res ; 2: fp16 split = gelu(acc+bias)
#define OFF_AH 0
#define OFF_AL 16384
#define OFF_B  32768
#define STAGE_BYTES 49152
#define NSTAGE 4
#define GEMM_SMEM (NSTAGE*STAGE_BYTES)   // 196608

template<int EPI>
__global__ __launch_bounds__(256, 1) void hmma_gemm(
    const __half* __restrict__ Ah, const __half* __restrict__ Al,
    const __half* __restrict__ B,
    const float* __restrict__ bias, const float* __restrict__ res,
    float* __restrict__ Cf, __half* __restrict__ Ch, __half* __restrict__ Cl,
    int M, int N, int K)
{
    extern __shared__ char smc[];
    const uint32_t sbase = smem_u32(smc);
    const int tid = threadIdx.x, wid = tid >> 5, lane = tid & 31;
    const int m0 = blockIdx.y * 128, n0 = blockIdx.x * 128;
    const int mw = (wid >> 2) * 64;   // warp m offset
    const int nw = (wid & 3) * 32;    // warp n offset

    float acc[4][4][4];
#pragma unroll
    for (int i = 0; i < 4; i++)
#pragma unroll
        for (int j = 0; j < 4; j++)
#pragma unroll
            for (int r = 0; r < 4; r++) acc[i][j][r] = 0.f;

    const int S = K >> 6;
    const int lrow = tid >> 1;
    const int lsq  = (tid & 1) * 4;

    auto load_stage = [&](int buf, int koff) {
        const uint32_t st = sbase + buf * STAGE_BYTES;
        const __half* gAh = Ah + (size_t)(m0 + lrow) * K + koff;
        const __half* gAl = Al + (size_t)(m0 + lrow) * K + koff;
        const __half* gB  = B  + (size_t)(n0 + lrow) * K + koff;
#pragma unroll
        for (int j = 0; j < 4; j++) {
            const int seg = lsq + j;
            const uint32_t so = SW128((uint32_t)(lrow * 128 + seg * 16));
            cp16(st + OFF_AH + so, gAh + seg * 8);
            cp16(st + OFF_AL + so, gAl + seg * 8);
            cp16(st + OFF_B  + so, gB  + seg * 8);
        }
    };

    // ldmatrix per-thread address components
    const int a_r = mw + (lane & 15);
    const int a_k = (lane >> 4) << 3;
    const int b_r = nw + (lane & 7);
    const int b_k = lane & 8;

    // prologue: stages 0..2
#pragma unroll
    for (int p = 0; p < NSTAGE - 1; p++) {
        load_stage(p, p << 6);
        CP_COMMIT();
    }

    for (int s = 0; s < S; s++) {
        CP_WAIT(NSTAGE - 2);          // stage s complete
        __syncthreads();              // all warps done with buffer (s-1)%4
        if (s + NSTAGE - 1 < S) load_stage((s + NSTAGE - 1) & 3, (s + NSTAGE - 1) << 6);
        CP_COMMIT();                  // empty group in tail keeps accounting exact

        const uint32_t st = sbase + (s & 3) * STAGE_BYTES;
#pragma unroll
        for (int kk = 0; kk < 4; kk++) {
            uint32_t ah[4][4], bh[4][2];
#pragma unroll
            for (int i = 0; i < 4; i++) {
                uint32_t ad = st + OFF_AH +
                    SW128((uint32_t)((a_r + i * 16) * 128 + (kk * 16 + a_k) * 2));
                LDSM_X4(ah[i][0], ah[i][1], ah[i][2], ah[i][3], ad);
            }
#pragma unroll
            for (int j = 0; j < 4; j++) {
                uint32_t off = SW128((uint32_t)((b_r + j * 8) * 128 + (kk * 16 + b_k) * 2));
                LDSM_X2(bh[j][0], bh[j][1], st + OFF_B + off);
            }
#pragma unroll
            for (int i = 0; i < 4; i++)
#pragma unroll
                for (int j = 0; j < 4; j++)
                    mma16816(acc[i][j], ah[i], bh[j]);
            // A-lo term (reuse ah regs)
#pragma unroll
            for (int i = 0; i < 4; i++) {
                uint32_t ad = st + OFF_AL +
                    SW128((uint32_t)((a_r + i * 16) * 128 + (kk * 16 + a_k) * 2));
                LDSM_X4(ah[i][0], ah[i][1], ah[i][2], ah[i][3], ad);
            }
#pragma unroll
            for (int i = 0; i < 4; i++)
#pragma unroll
                for (int j = 0; j < 4; j++)
                    mma16816(acc[i][j], ah[i], bh[j]);
        }
    }

    // ---------------- epilogue ----------------
    const int er = lane >> 2;
    const int ec = 2 * (lane & 3);
#pragma unroll
    for (int i = 0; i < 4; i++) {
        const int row0 = m0 + mw + i * 16 + er;
        const int row1 = row0 + 8;
#pragma unroll
        for (int j = 0; j < 4; j++) {
            const int col = n0 + nw + j * 8 + ec;
            const float b0 = bias[col], b1 = bias[col + 1];
            float v0 = acc[i][j][0] + b0;
            float v1 = acc[i][j][1] + b1;
            float v2 = acc[i][j][2] + b0;
            float v3 = acc[i][j][3] + b1;
            if (EPI == 1) {
                const float2 r0 = *(const float2*)(res + (size_t)row0 * N + col);
                const float2 r1 = *(const float2*)(res + (size_t)row1 * N + col);
                v0 += r0.x; v1 += r0.y; v2 += r1.x; v3 += r1.y;
            }
            if (EPI == 2) {
                v0 = 0.5f * v0 * (1.0f + erff(v0 * 0.70710678118654752f));
                v1 = 0.5f * v1 * (1.0f + erff(v1 * 0.70710678118654752f));
                v2 = 0.5f * v2 * (1.0f + erff(v2 * 0.70710678118654752f));
                v3 = 0.5f * v3 * (1.0f + erff(v3 * 0.70710678118654752f));
                __half2 h0 = __floats2half2_rn(v0, v1);
                __half2 h1 = __floats2half2_rn(v2, v3);
                __half2 l0 = __floats2half2_rn(v0 - __low2float(h0), v1 - __high2float(h0));
                __half2 l1 = __floats2half2_rn(v2 - __low2float(h1), v3 - __high2float(h1));
                *(__half2*)(Ch + (size_t)row0 * N + col) = h0;
                *(__half2*)(Cl + (size_t)row0 * N + col) = l0;
                *(__half2*)(Ch + (size_t)row1 * N + col) = h1;
                *(__half2*)(Cl + (size_t)row1 * N + col) = l1;
            } else {
                *(float2*)(Cf + (size_t)row0 * N + col) = make_float2(v0, v1);
                *(float2*)(Cf + (size_t)row1 * N + col) = make_float2(v2, v3);
            }
        }
    }
}

// ---------------- LayerNorm (writes fp16 hi/lo split) ------------------------
__global__ __launch_bounds__(256) void ln_kernel(
    const float* __restrict__ x, const float* __restrict__ g,
    const float* __restrict__ b, __half* __restrict__ oh,
    __half* __restrict__ ol)
{
    const int row = blockIdx.x;
    const float* xr = x + (size_t)row * DMODEL;
    const int tid = threadIdx.x;

    float v[4];
    float s = 0.f, ss = 0.f;
#pragma unroll
    for (int i = 0; i < 4; i++) {
        v[i] = xr[tid + i * 256];
        s += v[i];
        ss += v[i] * v[i];
    }
#pragma unroll
    for (int off = 16; off; off >>= 1) {
        s  += __shfl_xor_sync(0xffffffffu, s, off);
        ss += __shfl_xor_sync(0xffffffffu, ss, off);
    }
    __shared__ float rs[8], rss[8];
    const int warp = tid >> 5, lane = tid & 31;
    if (lane == 0) { rs[warp] = s; rss[warp] = ss; }
    __syncthreads();
    __shared__ float s_mu, s_inv;
    if (tid == 0) {
        float S = 0.f, SS = 0.f;
#pragma unroll
        for (int w = 0; w < 8; w++) { S += rs[w]; SS += rss[w]; }
        float mu = S * (1.0f / DMODEL);
        float var = SS * (1.0f / DMODEL) - mu * mu;
        s_mu = mu;
        s_inv = rsqrtf(var + LN_EPS);
    }
    __syncthreads();
    const float mu = s_mu, inv = s_inv;
#pragma unroll
    for (int i = 0; i < 4; i++) {
        int c = tid + i * 256;
        float o = (v[i] - mu) * inv * g[c] + b[c];
        __half hb = __float2half_rn(o);
        oh[(size_t)row * DMODEL + c] = hb;
        ol[(size_t)row * DMODEL + c] = __float2half_rn(o - __half2float(hb));
    }
}

// ---------------- Windowed attention (writes fp16 hi/lo split) ---------------
#define QT 64
#define KSPAN 320
#define SSTR 321
#define QKSTR 65
#define ATT_SMEM_FLOATS (QT*SSTR + QT*QKSTR + QT*QKSTR)

__global__ __launch_bounds__(256) void attn_kernel(
    const float* __restrict__ qkv, __half* __restrict__ ath,
    __half* __restrict__ atl)
{
    const int q0 = blockIdx.x * QT;
    const int h  = blockIdx.y;
    const int b  = blockIdx.z;

    extern __shared__ float smf[];
    float* S   = smf;
    float* Qs  = S + QT * SSTR;
    float* KVs = Qs + QT * QKSTR;

    const int tid = threadIdx.x;
    const int tx = tid & 15, ty = tid >> 4;
    const int kbase = q0 - WHALF;
    const float NEG_INF = __int_as_float(0xff800000);

    for (int idx = tid; idx < QT * 16; idx += 256) {
        int r = idx >> 4, seg = idx & 15;
        float4 v = *(const float4*)(qkv + ((size_t)(b * SEQ + q0 + r)) * 3 * DMODEL
                                    + h * HDIM + seg * 4);
        Qs[r * QKSTR + seg * 4 + 0] = v.x;
        Qs[r * QKSTR + seg * 4 + 1] = v.y;
        Qs[r * QKSTR + seg * 4 + 2] = v.z;
        Qs[r * QKSTR + seg * 4 + 3] = v.w;
    }

    for (int c = 0; c < 5; c++) {
        __syncthreads();
        for (int idx = tid; idx < 64 * 16; idx += 256) {
            int r = idx >> 4, seg = idx & 15;
            int kidx = kbase + c * 64 + r;
            float4 v = make_float4(0.f, 0.f, 0.f, 0.f);
            if (kidx >= 0 && kidx < SEQ)
                v = *(const float4*)(qkv + ((size_t)(b * SEQ + kidx)) * 3 * DMODEL
                                     + DMODEL + h * HDIM + seg * 4);
            KVs[r * QKSTR + seg * 4 + 0] = v.x;
            KVs[r * QKSTR + seg * 4 + 1] = v.y;
            KVs[r * QKSTR + seg * 4 + 2] = v.z;
            KVs[r * QKSTR + seg * 4 + 3] = v.w;
        }
        __syncthreads();

        float acc[4][4];
#pragma unroll
        for (int i = 0; i < 4; i++)
#pragma unroll
            for (int j = 0; j < 4; j++) acc[i][j] = 0.f;

#pragma unroll 8
        for (int d = 0; d < HDIM; d++) {
            float a[4], bb[4];
#pragma unroll
            for (int i = 0; i < 4; i++) a[i]  = Qs[(ty * 4 + i) * QKSTR + d];
#pragma unroll
            for (int j = 0; j < 4; j++) bb[j] = KVs[(tx * 4 + j) * QKSTR + d];
#pragma unroll
            for (int i = 0; i < 4; i++)
#pragma unroll
                for (int j = 0; j < 4; j++)
                    acc[i][j] = fmaf(a[i], bb[j], acc[i][j]);
        }

#pragma unroll
        for (int i = 0; i < 4; i++) {
            const int qr = ty * 4 + i;
#pragma unroll
            for (int j = 0; j < 4; j++) {
                const int kc = tx * 4 + j;
                const int rel = c * 64 + kc - qr;
                const int kidx = kbase + c * 64 + kc;
                bool ok = (rel >= 0) && (rel <= 2 * WHALF) && (kidx >= 0) && (kidx < SEQ);
                S[qr * SSTR + c * 64 + kc] = ok ? acc[i][j] * 0.125f : NEG_INF;
            }
        }
    }
    __syncthreads();

    {
        const int warp = tid >> 5, lane = tid & 31;
        for (int row = warp; row < QT; row += 8) {
            float* Sr = S + row * SSTR;
            float m = NEG_INF;
            for (int jj = lane; jj < KSPAN; jj += 32) m = fmaxf(m, Sr[jj]);
#pragma unroll
            for (int off = 16; off; off >>= 1)
                m = fmaxf(m, __shfl_xor_sync(0xffffffffu, m, off));
            float ssum = 0.f;
            for (int jj = lane; jj < KSPAN; jj += 32) {
                float e = expf(Sr[jj] - m);
                Sr[jj] = e;
                ssum += e;
            }
#pragma unroll
            for (int off = 16; off; off >>= 1)
                ssum += __shfl_xor_sync(0xffffffffu, ssum, off);
            float invs = 1.0f / ssum;
            for (int jj = lane; jj < KSPAN; jj += 32) Sr[jj] *= invs;
        }
    }

    float oacc[4][4];
#pragma unroll
    for (int i = 0; i < 4; i++)
#pragma unroll
        for (int j = 0; j < 4; j++) oacc[i][j] = 0.f;

    for (int c = 0; c < 5; c++) {
        __syncthreads();
        for (int idx = tid; idx < 64 * 16; idx += 256) {
            int r = idx >> 4, seg = idx & 15;
            int kidx = kbase + c * 64 + r;
            float4 v = make_float4(0.f, 0.f, 0.f, 0.f);
            if (kidx >= 0 && kidx < SEQ)
                v = *(const float4*)(qkv + ((size_t)(b * SEQ + kidx)) * 3 * DMODEL
                                     + 2 * DMODEL + h * HDIM + seg * 4);
            KVs[r * QKSTR + seg * 4 + 0] = v.x;
            KVs[r * QKSTR + seg * 4 + 1] = v.y;
            KVs[r * QKSTR + seg * 4 + 2] = v.z;
            KVs[r * QKSTR + seg * 4 + 3] = v.w;
        }
        __syncthreads();

#pragma unroll 8
        for (int j = 0; j < 64; j++) {
            float a[4], bb[4];
#pragma unroll
            for (int i = 0; i < 4; i++)  a[i]  = S[(ty * 4 + i) * SSTR + c * 64 + j];
#pragma unroll
            for (int jj = 0; jj < 4; jj++) bb[jj] = KVs[j * QKSTR + tx * 4 + jj];
#pragma unroll
            for (int i = 0; i < 4; i++)
#pragma unroll
                for (int jj = 0; jj < 4; jj++)
                    oacc[i][jj] = fmaf(a[i], bb[jj], oacc[i][jj]);
        }
    }

#pragma unroll
    for (int i = 0; i < 4; i++) {
        const int qr = ty * 4 + i;
#pragma unroll
        for (int j = 0; j < 4; j++) {
            const int d = tx * 4 + j;
            float v = oacc[i][j];
            __half hb = __float2half_rn(v);
            size_t off = ((size_t)(b * SEQ + q0 + qr)) * DMODEL + h * HDIM + d;
            ath[off] = hb;
            atl[off] = __float2half_rn(v - __half2float(hb));
        }
    }
}

// ---------------- launch -----------------------------------------------------
extern "C" void kernel_launch(void* const* d_in, const int* in_sizes, int n_in,
                              void* d_out, int out_size)
{
    const float* x      = (const float*)d_in[0];
    const float* qkv_w  = (const float*)d_in[1];
    const float* qkv_b  = (const float*)d_in[2];
    const float* out_w  = (const float*)d_in[3];
    const float* out_b  = (const float*)d_in[4];
    const float* ln1_g  = (const float*)d_in[5];
    const float* ln1_b  = (const float*)d_in[6];
    const float* ln2_g  = (const float*)d_in[7];
    const float* ln2_b  = (const float*)d_in[8];
    const float* ffn_w1 = (const float*)d_in[9];
    const float* ffn_b1 = (const float*)d_in[10];
    const float* ffn_w2 = (const float*)d_in[11];
    const float* ffn_b2 = (const float*)d_in[12];
    float* out = (float*)d_out;

    float *qkv, *x1;
    cudaGetSymbolAddress((void**)&qkv, g_qkv);
    cudaGetSymbolAddress((void**)&x1,  g_x1);

    __half *hh, *hl, *atth, *attl, *h2h, *h2l, *ffh, *ffl;
    cudaGetSymbolAddress((void**)&hh,   g_h_h);
    cudaGetSymbolAddress((void**)&hl,   g_h_l);
    cudaGetSymbolAddress((void**)&atth, g_att_h);
    cudaGetSymbolAddress((void**)&attl, g_att_l);
    cudaGetSymbolAddress((void**)&h2h,  g_h2_h);
    cudaGetSymbolAddress((void**)&h2l,  g_h2_l);
    cudaGetSymbolAddress((void**)&ffh,  g_ffn_h);
    cudaGetSymbolAddress((void**)&ffl,  g_ffn_l);

    __half *wq, *wo, *w1, *w2;
    cudaGetSymbolAddress((void**)&wq, g_wqkv);
    cudaGetSymbolAddress((void**)&wo, g_wout);
    cudaGetSymbolAddress((void**)&w1, g_wf1);
    cudaGetSymbolAddress((void**)&w2, g_wf2);

    const size_t att_smem = (size_t)ATT_SMEM_FLOATS * sizeof(float);
    cudaFuncSetAttribute(attn_kernel, cudaFuncAttributeMaxDynamicSharedMemorySize,
                         (int)att_smem);
    cudaFuncSetAttribute(hmma_gemm<0>, cudaFuncAttributeMaxDynamicSharedMemorySize, GEMM_SMEM);
    cudaFuncSetAttribute(hmma_gemm<1>, cudaFuncAttributeMaxDynamicSharedMemorySize, GEMM_SMEM);
    cudaFuncSetAttribute(hmma_gemm<2>, cudaFuncAttributeMaxDynamicSharedMemorySize, GEMM_SMEM);

    // 0) weight transpose -> fp16 [N,K]
    transpose_fp16<<<dim3(3*DMODEL/32, DMODEL/32), 256>>>(qkv_w, wq, DMODEL, 3*DMODEL);
    transpose_fp16<<<dim3(DMODEL/32,   DMODEL/32), 256>>>(out_w, wo, DMODEL, DMODEL);
    transpose_fp16<<<dim3(2*DMODEL/32, DMODEL/32), 256>>>(ffn_w1, w1, DMODEL, 2*DMODEL);
    transpose_fp16<<<dim3(DMODEL/32, 2*DMODEL/32), 256>>>(ffn_w2, w2, 2*DMODEL, DMODEL);

    // 1) LN1(x) -> h hi/lo
    ln_kernel<<<ROWS, 256>>>(x, ln1_g, ln1_b, hh, hl);
    // 2) qkv = h @ qkv_w + qkv_b  (f32)
    hmma_gemm<0><<<dim3(3*DMODEL/128, ROWS/128), 256, GEMM_SMEM>>>(
        hh, hl, wq, qkv_b, nullptr, qkv, nullptr, nullptr,
        ROWS, 3*DMODEL, DMODEL);
    // 3) windowed attention -> att hi/lo
    attn_kernel<<<dim3(SEQ/QT, NHEADS, BATCH), 256, att_smem>>>(qkv, atth, attl);
    // 4) x1 = x + att @ out_w + out_b (f32)
    hmma_gemm<1><<<dim3(DMODEL/128, ROWS/128), 256, GEMM_SMEM>>>(
        atth, attl, wo, out_b, x, x1, nullptr, nullptr,
        ROWS, DMODEL, DMODEL);
    // 5) LN2(x1) -> h2 hi/lo
    ln_kernel<<<ROWS, 256>>>(x1, ln2_g, ln2_b, h2h, h2l);
    // 6) ffn = gelu(h2 @ ffn_w1 + ffn_b1)  (fp16 split)
    hmma_gemm<2><<<dim3(2*DMODEL/128, ROWS/128), 256, GEMM_SMEM>>>(
        h2h, h2l, w1, ffn_b1, nullptr, nullptr, ffh, ffl,
        ROWS, 2*DMODEL, DMODEL);
    // 7) out = x1 + ffn @ ffn_w2 + ffn_b2 (f32)
    hmma_gemm<1><<<dim3(DMODEL/128, ROWS/128), 256, GEMM_SMEM>>>(
        ffh, ffl, w2, ffn_b2, x1, out, nullptr, nullptr,
        ROWS, DMODEL, 2*DMODEL);
}

// round 5
// speedup vs baseline: 3.3606x; 1.3512x over previous
#include <cuda_runtime.h>
#include <cuda_fp16.h>
#include <math.h>
#include <stdint.h>

// ---------------- problem constants ----------------
#define BATCH 2
#define SEQ   2048
#define DMODEL 1024
#define NHEADS 16
#define HDIM  64
#define ROWS  (BATCH*SEQ)          // 4096
#define WHALF 128
#define LN_EPS 1e-5f

// ---------------- scratch (device globals) ----------
__device__ float g_qkv [ROWS * 3 * DMODEL];    // f32 (attention consumes)
__device__ float g_x1  [ROWS * DMODEL];        // f32 (residual + LN2 input)

// fp16 activations (GEMM A operands)
__device__ __half g_h  [ROWS * DMODEL];
__device__ __half g_att[ROWS * DMODEL];
__device__ __half g_h2 [ROWS * DMODEL];
__device__ __half g_ffn[ROWS * 2 * DMODEL];

// transposed fp16 weights: [N, K] row-major
__device__ __half g_wqkv[3*DMODEL*DMODEL];
__device__ __half g_wout[DMODEL*DMODEL];
__device__ __half g_wf1 [2*DMODEL*DMODEL];
__device__ __half g_wf2 [2*DMODEL*DMODEL];

// ---------------- helpers ----------------------------------------------------
__device__ __forceinline__ uint32_t smem_u32(const void* p) {
    uint32_t a;
    asm("{ .reg .u64 t; cvta.to.shared.u64 t, %1; cvt.u32.u64 %0, t; }"
        : "=r"(a) : "l"(p));
    return a;
}
#define SW128(off) ((off) ^ (((off) >> 3) & 0x70))

__device__ __forceinline__ void cp16(uint32_t smem, const void* g) {
    asm volatile("cp.async.cg.shared.global [%0], [%1], 16;"
        :: "r"(smem), "l"(g) : "memory");
}
#define CP_COMMIT() asm volatile("cp.async.commit_group;" ::: "memory")
#define CP_WAIT(n)  asm volatile("cp.async.wait_group %0;" :: "n"(n) : "memory")

#define LDSM_X4(r0,r1,r2,r3,addr) \
    asm volatile("ldmatrix.sync.aligned.m8n8.x4.shared.b16 {%0,%1,%2,%3}, [%4];" \
        : "=r"(r0), "=r"(r1), "=r"(r2), "=r"(r3) : "r"(addr))
#define LDSM_X2(r0,r1,addr) \
    asm volatile("ldmatrix.sync.aligned.m8n8.x2.shared.b16 {%0,%1}, [%2];" \
        : "=r"(r0), "=r"(r1) : "r"(addr))

__device__ __forceinline__ void mma16816(float* d, const uint32_t* a, const uint32_t* b) {
    asm volatile(
        "mma.sync.aligned.m16n8k16.row.col.f32.f16.f16.f32 "
        "{%0,%1,%2,%3}, {%4,%5,%6,%7}, {%8,%9}, {%0,%1,%2,%3};"
        : "+f"(d[0]), "+f"(d[1]), "+f"(d[2]), "+f"(d[3])
        : "r"(a[0]), "r"(a[1]), "r"(a[2]), "r"(a[3]), "r"(b[0]), "r"(b[1]));
}

// ---------------- transpose weights: w [K,N] f32 -> t [N,K] fp16 -------------
__global__ __launch_bounds__(256) void transpose_fp16(
    const float* __restrict__ w, __half* __restrict__ t, int K, int N)
{
    __shared__ float tb[32][33];
    const int n0 = blockIdx.x * 32, k0 = blockIdx.y * 32;
    const int c = threadIdx.x & 31, r = threadIdx.x >> 5;
#pragma unroll
    for (int i = 0; i < 32; i += 8)
        tb[r + i][c] = w[(size_t)(k0 + r + i) * N + n0 + c];
    __syncthreads();
#pragma unroll
    for (int i = 0; i < 32; i += 8)
        t[(size_t)(n0 + r + i) * K + k0 + c] = __float2half_rn(tb[c][r + i]);
}

// ---------------- HMMA GEMM --------------------------------------------------
// C[M,N] = A[M,K] @ B^T ; A fp16 [M,K], B fp16 [N,K], single term.
// 128x128 CTA tile, 8 warps of 64x32, K-step 64, 4-stage cp.async pipeline.
// EPI 0: f32 = acc+bias ; 1: f32 = acc+bias+res ; 2: fp16 = gelu(acc+bias)
#define OFF_A 0
#define OFF_B 16384
#define STAGE_BYTES 32768
#define NSTAGE 4
#define GEMM_SMEM (NSTAGE*STAGE_BYTES)   // 131072

template<int EPI>
__global__ __launch_bounds__(256, 1) void hmma_gemm(
    const __half* __restrict__ A, const __half* __restrict__ B,
    const float* __restrict__ bias, const float* __restrict__ res,
    float* __restrict__ Cf, __half* __restrict__ Ch,
    int M, int N, int K)
{
    extern __shared__ char smc[];
    const uint32_t sbase = smem_u32(smc);
    const int tid = threadIdx.x, wid = tid >> 5, lane = tid & 31;
    const int m0 = blockIdx.y * 128, n0 = blockIdx.x * 128;
    const int mw = (wid >> 2) * 64;   // warp m offset
    const int nw = (wid & 3) * 32;    // warp n offset

    float acc[4][4][4];
#pragma unroll
    for (int i = 0; i < 4; i++)
#pragma unroll
        for (int j = 0; j < 4; j++)
#pragma unroll
            for (int r = 0; r < 4; r++) acc[i][j][r] = 0.f;

    const int S = K >> 6;
    const int lrow = tid >> 1;
    const int lsq  = (tid & 1) * 4;

    auto load_stage = [&](int buf, int koff) {
        const uint32_t st = sbase + buf * STAGE_BYTES;
        const __half* gA = A + (size_t)(m0 + lrow) * K + koff;
        const __half* gB = B + (size_t)(n0 + lrow) * K + koff;
#pragma unroll
        for (int j = 0; j < 4; j++) {
            const int seg = lsq + j;
            const uint32_t so = SW128((uint32_t)(lrow * 128 + seg * 16));
            cp16(st + OFF_A + so, gA + seg * 8);
            cp16(st + OFF_B + so, gB + seg * 8);
        }
    };

    // ldmatrix per-thread address components
    const int a_r = mw + (lane & 15);
    const int a_k = (lane >> 4) << 3;
    const int b_r = nw + (lane & 7);
    const int b_k = lane & 8;

    // prologue
#pragma unroll
    for (int p = 0; p < NSTAGE - 1; p++) {
        load_stage(p, p << 6);
        CP_COMMIT();
    }

    for (int s = 0; s < S; s++) {
        CP_WAIT(NSTAGE - 2);
        __syncthreads();
        if (s + NSTAGE - 1 < S) load_stage((s + NSTAGE - 1) & 3, (s + NSTAGE - 1) << 6);
        CP_COMMIT();

        const uint32_t st = sbase + (s & 3) * STAGE_BYTES;
#pragma unroll
        for (int kk = 0; kk < 4; kk++) {
            uint32_t ah[4][4], bh[4][2];
#pragma unroll
            for (int i = 0; i < 4; i++) {
                uint32_t ad = st + OFF_A +
                    SW128((uint32_t)((a_r + i * 16) * 128 + (kk * 16 + a_k) * 2));
                LDSM_X4(ah[i][0], ah[i][1], ah[i][2], ah[i][3], ad);
            }
#pragma unroll
            for (int j = 0; j < 4; j++) {
                uint32_t off = SW128((uint32_t)((b_r + j * 8) * 128 + (kk * 16 + b_k) * 2));
                LDSM_X2(bh[j][0], bh[j][1], st + OFF_B + off);
            }
#pragma unroll
            for (int i = 0; i < 4; i++)
#pragma unroll
                for (int j = 0; j < 4; j++)
                    mma16816(acc[i][j], ah[i], bh[j]);
        }
    }

    // ---------------- epilogue ----------------
    const int er = lane >> 2;
    const int ec = 2 * (lane & 3);
#pragma unroll
    for (int i = 0; i < 4; i++) {
        const int row0 = m0 + mw + i * 16 + er;
        const int row1 = row0 + 8;
#pragma unroll
        for (int j = 0; j < 4; j++) {
            const int col = n0 + nw + j * 8 + ec;
            const float b0 = bias[col], b1 = bias[col + 1];
            float v0 = acc[i][j][0] + b0;
            float v1 = acc[i][j][1] + b1;
            float v2 = acc[i][j][2] + b0;
            float v3 = acc[i][j][3] + b1;
            if (EPI == 1) {
                const float2 r0 = *(const float2*)(res + (size_t)row0 * N + col);
                const float2 r1 = *(const float2*)(res + (size_t)row1 * N + col);
                v0 += r0.x; v1 += r0.y; v2 += r1.x; v3 += r1.y;
            }
            if (EPI == 2) {
                v0 = 0.5f * v0 * (1.0f + erff(v0 * 0.70710678118654752f));
                v1 = 0.5f * v1 * (1.0f + erff(v1 * 0.70710678118654752f));
                v2 = 0.5f * v2 * (1.0f + erff(v2 * 0.70710678118654752f));
                v3 = 0.5f * v3 * (1.0f + erff(v3 * 0.70710678118654752f));
                *(__half2*)(Ch + (size_t)row0 * N + col) = __floats2half2_rn(v0, v1);
                *(__half2*)(Ch + (size_t)row1 * N + col) = __floats2half2_rn(v2, v3);
            } else {
                *(float2*)(Cf + (size_t)row0 * N + col) = make_float2(v0, v1);
                *(float2*)(Cf + (size_t)row1 * N + col) = make_float2(v2, v3);
            }
        }
    }
}

// ---------------- LayerNorm (writes fp16) ------------------------------------
__global__ __launch_bounds__(256) void ln_kernel(
    const float* __restrict__ x, const float* __restrict__ g,
    const float* __restrict__ b, __half* __restrict__ oh)
{
    const int row = blockIdx.x;
    const float* xr = x + (size_t)row * DMODEL;
    const int tid = threadIdx.x;

    float v[4];
    float s = 0.f, ss = 0.f;
#pragma unroll
    for (int i = 0; i < 4; i++) {
        v[i] = xr[tid + i * 256];
        s += v[i];
        ss += v[i] * v[i];
    }
#pragma unroll
    for (int off = 16; off; off >>= 1) {
        s  += __shfl_xor_sync(0xffffffffu, s, off);
        ss += __shfl_xor_sync(0xffffffffu, ss, off);
    }
    __shared__ float rs[8], rss[8];
    const int warp = tid >> 5, lane = tid & 31;
    if (lane == 0) { rs[warp] = s; rss[warp] = ss; }
    __syncthreads();
    __shared__ float s_mu, s_inv;
    if (tid == 0) {
        float S = 0.f, SS = 0.f;
#pragma unroll
        for (int w = 0; w < 8; w++) { S += rs[w]; SS += rss[w]; }
        float mu = S * (1.0f / DMODEL);
        float var = SS * (1.0f / DMODEL) - mu * mu;
        s_mu = mu;
        s_inv = rsqrtf(var + LN_EPS);
    }
    __syncthreads();
    const float mu = s_mu, inv = s_inv;
#pragma unroll
    for (int i = 0; i < 4; i++) {
        int c = tid + i * 256;
        float o = (v[i] - mu) * inv * g[c] + b[c];
        oh[(size_t)row * DMODEL + c] = __float2half_rn(o);
    }
}

// ---------------- Windowed attention (writes fp16) ---------------------------
#define QT 64
#define KSPAN 320
#define SSTR 321
#define QKSTR 65
#define ATT_SMEM_FLOATS (QT*SSTR + QT*QKSTR + QT*QKSTR)

__global__ __launch_bounds__(256) void attn_kernel(
    const float* __restrict__ qkv, __half* __restrict__ ath)
{
    const int q0 = blockIdx.x * QT;
    const int h  = blockIdx.y;
    const int b  = blockIdx.z;

    extern __shared__ float smf[];
    float* S   = smf;
    float* Qs  = S + QT * SSTR;
    float* KVs = Qs + QT * QKSTR;

    const int tid = threadIdx.x;
    const int tx = tid & 15, ty = tid >> 4;
    const int kbase = q0 - WHALF;
    const float NEG_INF = __int_as_float(0xff800000);

    for (int idx = tid; idx < QT * 16; idx += 256) {
        int r = idx >> 4, seg = idx & 15;
        float4 v = *(const float4*)(qkv + ((size_t)(b * SEQ + q0 + r)) * 3 * DMODEL
                                    + h * HDIM + seg * 4);
        Qs[r * QKSTR + seg * 4 + 0] = v.x;
        Qs[r * QKSTR + seg * 4 + 1] = v.y;
        Qs[r * QKSTR + seg * 4 + 2] = v.z;
        Qs[r * QKSTR + seg * 4 + 3] = v.w;
    }

    for (int c = 0; c < 5; c++) {
        __syncthreads();
        for (int idx = tid; idx < 64 * 16; idx += 256) {
            int r = idx >> 4, seg = idx & 15;
            int kidx = kbase + c * 64 + r;
            float4 v = make_float4(0.f, 0.f, 0.f, 0.f);
            if (kidx >= 0 && kidx < SEQ)
                v = *(const float4*)(qkv + ((size_t)(b * SEQ + kidx)) * 3 * DMODEL
                                     + DMODEL + h * HDIM + seg * 4);
            KVs[r * QKSTR + seg * 4 + 0] = v.x;
            KVs[r * QKSTR + seg * 4 + 1] = v.y;
            KVs[r * QKSTR + seg * 4 + 2] = v.z;
            KVs[r * QKSTR + seg * 4 + 3] = v.w;
        }
        __syncthreads();

        float acc[4][4];
#pragma unroll
        for (int i = 0; i < 4; i++)
#pragma unroll
            for (int j = 0; j < 4; j++) acc[i][j] = 0.f;

#pragma unroll 8
        for (int d = 0; d < HDIM; d++) {
            float a[4], bb[4];
#pragma unroll
            for (int i = 0; i < 4; i++) a[i]  = Qs[(ty * 4 + i) * QKSTR + d];
#pragma unroll
            for (int j = 0; j < 4; j++) bb[j] = KVs[(tx * 4 + j) * QKSTR + d];
#pragma unroll
            for (int i = 0; i < 4; i++)
#pragma unroll
                for (int j = 0; j < 4; j++)
                    acc[i][j] = fmaf(a[i], bb[j], acc[i][j]);
        }

#pragma unroll
        for (int i = 0; i < 4; i++) {
            const int qr = ty * 4 + i;
#pragma unroll
            for (int j = 0; j < 4; j++) {
                const int kc = tx * 4 + j;
                const int rel = c * 64 + kc - qr;
                const int kidx = kbase + c * 64 + kc;
                bool ok = (rel >= 0) && (rel <= 2 * WHALF) && (kidx >= 0) && (kidx < SEQ);
                S[qr * SSTR + c * 64 + kc] = ok ? acc[i][j] * 0.125f : NEG_INF;
            }
        }
    }
    __syncthreads();

    {
        const int warp = tid >> 5, lane = tid & 31;
        for (int row = warp; row < QT; row += 8) {
            float* Sr = S + row * SSTR;
            float m = NEG_INF;
            for (int jj = lane; jj < KSPAN; jj += 32) m = fmaxf(m, Sr[jj]);
#pragma unroll
            for (int off = 16; off; off >>= 1)
                m = fmaxf(m, __shfl_xor_sync(0xffffffffu, m, off));
            float ssum = 0.f;
            for (int jj = lane; jj < KSPAN; jj += 32) {
                float e = expf(Sr[jj] - m);
                Sr[jj] = e;
                ssum += e;
            }
#pragma unroll
            for (int off = 16; off; off >>= 1)
                ssum += __shfl_xor_sync(0xffffffffu, ssum, off);
            float invs = 1.0f / ssum;
            for (int jj = lane; jj < KSPAN; jj += 32) Sr[jj] *= invs;
        }
    }

    float oacc[4][4];
#pragma unroll
    for (int i = 0; i < 4; i++)
#pragma unroll
        for (int j = 0; j < 4; j++) oacc[i][j] = 0.f;

    for (int c = 0; c < 5; c++) {
        __syncthreads();
        for (int idx = tid; idx < 64 * 16; idx += 256) {
            int r = idx >> 4, seg = idx & 15;
            int kidx = kbase + c * 64 + r;
            float4 v = make_float4(0.f, 0.f, 0.f, 0.f);
            if (kidx >= 0 && kidx < SEQ)
                v = *(const float4*)(qkv + ((size_t)(b * SEQ + kidx)) * 3 * DMODEL
                                     + 2 * DMODEL + h * HDIM + seg * 4);
            KVs[r * QKSTR + seg * 4 + 0] = v.x;
            KVs[r * QKSTR + seg * 4 + 1] = v.y;
            KVs[r * QKSTR + seg * 4 + 2] = v.z;
            KVs[r * QKSTR + seg * 4 + 3] = v.w;
        }
        __syncthreads();

#pragma unroll 8
        for (int j = 0; j < 64; j++) {
            float a[4], bb[4];
#pragma unroll
            for (int i = 0; i < 4; i++)  a[i]  = S[(ty * 4 + i) * SSTR + c * 64 + j];
#pragma unroll
            for (int jj = 0; jj < 4; jj++) bb[jj] = KVs[j * QKSTR + tx * 4 + jj];
#pragma unroll
            for (int i = 0; i < 4; i++)
#pragma unroll
                for (int jj = 0; jj < 4; jj++)
                    oacc[i][jj] = fmaf(a[i], bb[jj], oacc[i][jj]);
        }
    }

#pragma unroll
    for (int i = 0; i < 4; i++) {
        const int qr = ty * 4 + i;
#pragma unroll
        for (int j = 0; j < 4; j++) {
            const int d = tx * 4 + j;
            ath[((size_t)(b * SEQ + q0 + qr)) * DMODEL + h * HDIM + d] =
                __float2half_rn(oacc[i][j]);
        }
    }
}

// ---------------- launch -----------------------------------------------------
extern "C" void kernel_launch(void* const* d_in, const int* in_sizes, int n_in,
                              void* d_out, int out_size)
{
    const float* x      = (const float*)d_in[0];
    const float* qkv_w  = (const float*)d_in[1];
    const float* qkv_b  = (const float*)d_in[2];
    const float* out_w  = (const float*)d_in[3];
    const float* out_b  = (const float*)d_in[4];
    const float* ln1_g  = (const float*)d_in[5];
    const float* ln1_b  = (const float*)d_in[6];
    const float* ln2_g  = (const float*)d_in[7];
    const float* ln2_b  = (const float*)d_in[8];
    const float* ffn_w1 = (const float*)d_in[9];
    const float* ffn_b1 = (const float*)d_in[10];
    const float* ffn_w2 = (const float*)d_in[11];
    const float* ffn_b2 = (const float*)d_in[12];
    float* out = (float*)d_out;

    float *qkv, *x1;
    cudaGetSymbolAddress((void**)&qkv, g_qkv);
    cudaGetSymbolAddress((void**)&x1,  g_x1);

    __half *hh, *atth, *h2h, *ffh;
    cudaGetSymbolAddress((void**)&hh,   g_h);
    cudaGetSymbolAddress((void**)&atth, g_att);
    cudaGetSymbolAddress((void**)&h2h,  g_h2);
    cudaGetSymbolAddress((void**)&ffh,  g_ffn);

    __half *wq, *wo, *w1, *w2;
    cudaGetSymbolAddress((void**)&wq, g_wqkv);
    cudaGetSymbolAddress((void**)&wo, g_wout);
    cudaGetSymbolAddress((void**)&w1, g_wf1);
    cudaGetSymbolAddress((void**)&w2, g_wf2);

    const size_t att_smem = (size_t)ATT_SMEM_FLOATS * sizeof(float);
    cudaFuncSetAttribute(attn_kernel, cudaFuncAttributeMaxDynamicSharedMemorySize,
                         (int)att_smem);
    cudaFuncSetAttribute(hmma_gemm<0>, cudaFuncAttributeMaxDynamicSharedMemorySize, GEMM_SMEM);
    cudaFuncSetAttribute(hmma_gemm<1>, cudaFuncAttributeMaxDynamicSharedMemorySize, GEMM_SMEM);
    cudaFuncSetAttribute(hmma_gemm<2>, cudaFuncAttributeMaxDynamicSharedMemorySize, GEMM_SMEM);

    // 0) weight transpose -> fp16 [N,K]
    transpose_fp16<<<dim3(3*DMODEL/32, DMODEL/32), 256>>>(qkv_w, wq, DMODEL, 3*DMODEL);
    transpose_fp16<<<dim3(DMODEL/32,   DMODEL/32), 256>>>(out_w, wo, DMODEL, DMODEL);
    transpose_fp16<<<dim3(2*DMODEL/32, DMODEL/32), 256>>>(ffn_w1, w1, DMODEL, 2*DMODEL);
    transpose_fp16<<<dim3(DMODEL/32, 2*DMODEL/32), 256>>>(ffn_w2, w2, 2*DMODEL, DMODEL);

    // 1) LN1(x) -> h (fp16)
    ln_kernel<<<ROWS, 256>>>(x, ln1_g, ln1_b, hh);
    // 2) qkv = h @ qkv_w + qkv_b  (f32)
    hmma_gemm<0><<<dim3(3*DMODEL/128, ROWS/128), 256, GEMM_SMEM>>>(
        hh, wq, qkv_b, nullptr, qkv, nullptr, ROWS, 3*DMODEL, DMODEL);
    // 3) windowed attention -> att (fp16)
    attn_kernel<<<dim3(SEQ/QT, NHEADS, BATCH), 256, att_smem>>>(qkv, atth);
    // 4) x1 = x + att @ out_w + out_b (f32)
    hmma_gemm<1><<<dim3(DMODEL/128, ROWS/128), 256, GEMM_SMEM>>>(
        atth, wo, out_b, x, x1, nullptr, ROWS, DMODEL, DMODEL);
    // 5) LN2(x1) -> h2 (fp16)
    ln_kernel<<<ROWS, 256>>>(x1, ln2_g, ln2_b, h2h);
    // 6) ffn = gelu(h2 @ ffn_w1 + ffn_b1)  (fp16)
    hmma_gemm<2><<<dim3(2*DMODEL/128, ROWS/128), 256, GEMM_SMEM>>>(
        h2h, w1, ffn_b1, nullptr, nullptr, ffh, ROWS, 2*DMODEL, DMODEL);
    // 7) out = x1 + ffn @ ffn_w2 + ffn_b2 (f32)
    hmma_gemm<1><<<dim3(DMODEL/128, ROWS/128), 256, GEMM_SMEM>>>(
        ffh, w2, ffn_b2, x1, out, nullptr, ROWS, DMODEL, 2*DMODEL);
}

// round 6
// speedup vs baseline: 4.3400x; 1.2914x over previous
#include <cuda_runtime.h>
#include <cuda_fp16.h>
#include <math.h>
#include <stdint.h>

// ---------------- problem constants ----------------
#define BATCH 2
#define SEQ   2048
#define DMODEL 1024
#define NHEADS 16
#define HDIM  64
#define ROWS  (BATCH*SEQ)          // 4096
#define WHALF 128
#define LN_EPS 1e-5f

// ---------------- scratch (device globals) ----------
__device__ float  g_x1 [ROWS * DMODEL];          // f32 residual / LN2 input
__device__ __half g_qkv[ROWS * 3 * DMODEL];      // fp16 qkv
__device__ __half g_h  [ROWS * DMODEL];
__device__ __half g_att[ROWS * DMODEL];
__device__ __half g_h2 [ROWS * DMODEL];
__device__ __half g_ffn[ROWS * 2 * DMODEL];

// transposed fp16 weights: [N, K] row-major
__device__ __half g_wqkv[3*DMODEL*DMODEL];
__device__ __half g_wout[DMODEL*DMODEL];
__device__ __half g_wf1 [2*DMODEL*DMODEL];
__device__ __half g_wf2 [2*DMODEL*DMODEL];

// ---------------- helpers ----------------------------------------------------
__device__ __forceinline__ uint32_t smem_u32(const void* p) {
    uint32_t a;
    asm("{ .reg .u64 t; cvta.to.shared.u64 t, %1; cvt.u32.u64 %0, t; }"
        : "=r"(a) : "l"(p));
    return a;
}
#define SW128(off) ((off) ^ (((off) >> 3) & 0x70))

__device__ __forceinline__ void cp16(uint32_t smem, const void* g) {
    asm volatile("cp.async.cg.shared.global [%0], [%1], 16;"
        :: "r"(smem), "l"(g) : "memory");
}
__device__ __forceinline__ void cp16z(uint32_t smem, const void* g, bool valid) {
    int sz = valid ? 16 : 0;
    asm volatile("cp.async.cg.shared.global [%0], [%1], 16, %2;"
        :: "r"(smem), "l"(g), "r"(sz) : "memory");
}
#define CP_COMMIT() asm volatile("cp.async.commit_group;" ::: "memory")
#define CP_WAIT(n)  asm volatile("cp.async.wait_group %0;" :: "n"(n) : "memory")

#define LDSM_X4(r0,r1,r2,r3,addr) \
    asm volatile("ldmatrix.sync.aligned.m8n8.x4.shared.b16 {%0,%1,%2,%3}, [%4];" \
        : "=r"(r0), "=r"(r1), "=r"(r2), "=r"(r3) : "r"(addr))
#define LDSM_X2(r0,r1,addr) \
    asm volatile("ldmatrix.sync.aligned.m8n8.x2.shared.b16 {%0,%1}, [%2];" \
        : "=r"(r0), "=r"(r1) : "r"(addr))

__device__ __forceinline__ void mma16816(float* d, const uint32_t* a, const uint32_t* b) {
    asm volatile(
        "mma.sync.aligned.m16n8k16.row.col.f32.f16.f16.f32 "
        "{%0,%1,%2,%3}, {%4,%5,%6,%7}, {%8,%9}, {%0,%1,%2,%3};"
        : "+f"(d[0]), "+f"(d[1]), "+f"(d[2]), "+f"(d[3])
        : "r"(a[0]), "r"(a[1]), "r"(a[2]), "r"(a[3]), "r"(b[0]), "r"(b[1]));
}

// ---------------- transpose weights: w [K,N] f32 -> t [N,K] fp16 -------------
__global__ __launch_bounds__(256) void transpose_fp16(
    const float* __restrict__ w, __half* __restrict__ t, int K, int N)
{
    __shared__ float tb[32][33];
    const int n0 = blockIdx.x * 32, k0 = blockIdx.y * 32;
    const int c = threadIdx.x & 31, r = threadIdx.x >> 5;
#pragma unroll
    for (int i = 0; i < 32; i += 8)
        tb[r + i][c] = w[(size_t)(k0 + r + i) * N + n0 + c];
    __syncthreads();
#pragma unroll
    for (int i = 0; i < 32; i += 8)
        t[(size_t)(n0 + r + i) * K + k0 + c] = __float2half_rn(tb[c][r + i]);
}

// ---------------- HMMA GEMM --------------------------------------------------
// C[M,N] = A[M,K] @ B^T ; A fp16 [M,K], B fp16 [N,K].
// EPI 1: f32 = acc+bias+res ; 2: fp16 = gelu(acc+bias) ; 3: fp16 = acc+bias
#define OFF_A 0
#define OFF_B 16384
#define STAGE_BYTES 32768
#define NSTAGE 4
#define GEMM_SMEM (NSTAGE*STAGE_BYTES)   // 131072

template<int EPI>
__global__ __launch_bounds__(256, 1) void hmma_gemm(
    const __half* __restrict__ A, const __half* __restrict__ B,
    const float* __restrict__ bias, const float* __restrict__ res,
    float* __restrict__ Cf, __half* __restrict__ Ch,
    int M, int N, int K)
{
    extern __shared__ char smc[];
    const uint32_t sbase = smem_u32(smc);
    const int tid = threadIdx.x, wid = tid >> 5, lane = tid & 31;
    const int m0 = blockIdx.y * 128, n0 = blockIdx.x * 128;
    const int mw = (wid >> 2) * 64;
    const int nw = (wid & 3) * 32;

    float acc[4][4][4];
#pragma unroll
    for (int i = 0; i < 4; i++)
#pragma unroll
        for (int j = 0; j < 4; j++)
#pragma unroll
            for (int r = 0; r < 4; r++) acc[i][j][r] = 0.f;

    const int S = K >> 6;
    const int lrow = tid >> 1;
    const int lsq  = (tid & 1) * 4;

    auto load_stage = [&](int buf, int koff) {
        const uint32_t st = sbase + buf * STAGE_BYTES;
        const __half* gA = A + (size_t)(m0 + lrow) * K + koff;
        const __half* gB = B + (size_t)(n0 + lrow) * K + koff;
#pragma unroll
        for (int j = 0; j < 4; j++) {
            const int seg = lsq + j;
            const uint32_t so = SW128((uint32_t)(lrow * 128 + seg * 16));
            cp16(st + OFF_A + so, gA + seg * 8);
            cp16(st + OFF_B + so, gB + seg * 8);
        }
    };

    const int a_r = mw + (lane & 15);
    const int a_k = (lane >> 4) << 3;
    const int b_r = nw + (lane & 7);
    const int b_k = lane & 8;

#pragma unroll
    for (int p = 0; p < NSTAGE - 1; p++) {
        load_stage(p, p << 6);
        CP_COMMIT();
    }

    for (int s = 0; s < S; s++) {
        CP_WAIT(NSTAGE - 2);
        __syncthreads();
        if (s + NSTAGE - 1 < S) load_stage((s + NSTAGE - 1) & 3, (s + NSTAGE - 1) << 6);
        CP_COMMIT();

        const uint32_t st = sbase + (s & 3) * STAGE_BYTES;
#pragma unroll
        for (int kk = 0; kk < 4; kk++) {
            uint32_t ah[4][4], bh[4][2];
#pragma unroll
            for (int i = 0; i < 4; i++) {
                uint32_t ad = st + OFF_A +
                    SW128((uint32_t)((a_r + i * 16) * 128 + (kk * 16 + a_k) * 2));
                LDSM_X4(ah[i][0], ah[i][1], ah[i][2], ah[i][3], ad);
            }
#pragma unroll
            for (int j = 0; j < 4; j++) {
                uint32_t off = SW128((uint32_t)((b_r + j * 8) * 128 + (kk * 16 + b_k) * 2));
                LDSM_X2(bh[j][0], bh[j][1], st + OFF_B + off);
            }
#pragma unroll
            for (int i = 0; i < 4; i++)
#pragma unroll
                for (int j = 0; j < 4; j++)
                    mma16816(acc[i][j], ah[i], bh[j]);
        }
    }

    // ---------------- epilogue ----------------
    const int er = lane >> 2;
    const int ec = 2 * (lane & 3);
#pragma unroll
    for (int i = 0; i < 4; i++) {
        const int row0 = m0 + mw + i * 16 + er;
        const int row1 = row0 + 8;
#pragma unroll
        for (int j = 0; j < 4; j++) {
            const int col = n0 + nw + j * 8 + ec;
            const float b0 = bias[col], b1 = bias[col + 1];
            float v0 = acc[i][j][0] + b0;
            float v1 = acc[i][j][1] + b1;
            float v2 = acc[i][j][2] + b0;
            float v3 = acc[i][j][3] + b1;
            if (EPI == 1) {
                const float2 r0 = *(const float2*)(res + (size_t)row0 * N + col);
                const float2 r1 = *(const float2*)(res + (size_t)row1 * N + col);
                v0 += r0.x; v1 += r0.y; v2 += r1.x; v3 += r1.y;
                *(float2*)(Cf + (size_t)row0 * N + col) = make_float2(v0, v1);
                *(float2*)(Cf + (size_t)row1 * N + col) = make_float2(v2, v3);
            }
            if (EPI == 2) {
                v0 = 0.5f * v0 * (1.0f + erff(v0 * 0.70710678118654752f));
                v1 = 0.5f * v1 * (1.0f + erff(v1 * 0.70710678118654752f));
                v2 = 0.5f * v2 * (1.0f + erff(v2 * 0.70710678118654752f));
                v3 = 0.5f * v3 * (1.0f + erff(v3 * 0.70710678118654752f));
                *(__half2*)(Ch + (size_t)row0 * N + col) = __floats2half2_rn(v0, v1);
                *(__half2*)(Ch + (size_t)row1 * N + col) = __floats2half2_rn(v2, v3);
            }
            if (EPI == 3) {
                *(__half2*)(Ch + (size_t)row0 * N + col) = __floats2half2_rn(v0, v1);
                *(__half2*)(Ch + (size_t)row1 * N + col) = __floats2half2_rn(v2, v3);
            }
        }
    }
}

// ---------------- LayerNorm (writes fp16) ------------------------------------
__global__ __launch_bounds__(256) void ln_kernel(
    const float* __restrict__ x, const float* __restrict__ g,
    const float* __restrict__ b, __half* __restrict__ oh)
{
    const int row = blockIdx.x;
    const float* xr = x + (size_t)row * DMODEL;
    const int tid = threadIdx.x;

    float v[4];
    float s = 0.f, ss = 0.f;
#pragma unroll
    for (int i = 0; i < 4; i++) {
        v[i] = xr[tid + i * 256];
        s += v[i];
        ss += v[i] * v[i];
    }
#pragma unroll
    for (int off = 16; off; off >>= 1) {
        s  += __shfl_xor_sync(0xffffffffu, s, off);
        ss += __shfl_xor_sync(0xffffffffu, ss, off);
    }
    __shared__ float rs[8], rss[8];
    const int warp = tid >> 5, lane = tid & 31;
    if (lane == 0) { rs[warp] = s; rss[warp] = ss; }
    __syncthreads();
    __shared__ float s_mu, s_inv;
    if (tid == 0) {
        float S = 0.f, SS = 0.f;
#pragma unroll
        for (int w = 0; w < 8; w++) { S += rs[w]; SS += rss[w]; }
        float mu = S * (1.0f / DMODEL);
        float var = SS * (1.0f / DMODEL) - mu * mu;
        s_mu = mu;
        s_inv = rsqrtf(var + LN_EPS);
    }
    __syncthreads();
    const float mu = s_mu, inv = s_inv;
#pragma unroll
    for (int i = 0; i < 4; i++) {
        int c = tid + i * 256;
        float o = (v[i] - mu) * inv * g[c] + b[c];
        oh[(size_t)row * DMODEL + c] = __float2half_rn(o);
    }
}

// ---------------- HMMA windowed attention ------------------------------------
// Block = (b, h, 64 queries). Key span 320 = 5 chunks of 64.
// fp16 Q/K/V from fp16 qkv; f32 scores+softmax in smem; fp16 P; HMMA P@V.
#define QT 64
#define KSPAN 320
#define SSTR 321                    // f32 score row stride
#define PSTR 328                    // fp16 P / V^T row stride (656B: conflict-free)
#define S_OFF  0
#define PS_OFF 82176                // 64*321*4
#define VT_OFF 124160               // +64*328*2
#define Q_OFF  166144               // +64*328*2
#define K_OFF  174336               // +8192
#define ATT_SMEM 190720             // +2*8192

__global__ __launch_bounds__(256, 1) void attn_kernel(
    const __half* __restrict__ qkv, __half* __restrict__ ath)
{
    extern __shared__ char smc[];
    const uint32_t sbase = smem_u32(smc);
    float*  Sf = (float*)(smc + S_OFF);
    __half* Ps = (__half*)(smc + PS_OFF);
    __half* VT = (__half*)(smc + VT_OFF);

    const int q0 = blockIdx.x * QT;
    const int h  = blockIdx.y;
    const int b  = blockIdx.z;
    const int tid = threadIdx.x, wid = tid >> 5, lane = tid & 31;
    const int kbase = q0 - WHALF;
    const float NEG_INF = __int_as_float(0xff800000);

    const size_t qkv_row = 3 * DMODEL;
    const __half* qbase = qkv + (size_t)(b * SEQ) * qkv_row + h * HDIM;

    // warp tiling: rows mw..mw+15, chunk-cols nw2..nw2+31
    const int mw  = (wid & 3) * 16;
    const int nw2 = (wid >> 2) * 32;
    const int er = lane >> 2, ec = 2 * (lane & 3);

    // ---- prologue: Q tile + K chunk 0 via cp.async ----
    {
        const int r = tid >> 2, seg0 = (tid & 3) * 2;   // 64 rows x 8 segs, 2/thread
#pragma unroll
        for (int j = 0; j < 2; j++) {
            const int seg = seg0 + j;
            cp16(sbase + Q_OFF + SW128((uint32_t)(r * 128 + seg * 16)),
                 qbase + (size_t)(q0 + r) * qkv_row + seg * 8);
            const int kidx = kbase + r;
            const bool ok = (kidx >= 0) && (kidx < SEQ);
            const int kc = ok ? kidx : 0;
            cp16z(sbase + K_OFF + SW128((uint32_t)(r * 128 + seg * 16)),
                  qbase + DMODEL + (size_t)kc * qkv_row + seg * 8, ok);
        }
        CP_COMMIT();
    }

    // ---- pass A: scores (5 chunks, K double-buffered) ----
    for (int c = 0; c < 5; c++) {
        __syncthreads();   // previous chunk's MMA done before overwriting its buffer
        if (c + 1 < 5) {
            const int buf = (c + 1) & 1;
            const int r = tid >> 2, seg0 = (tid & 3) * 2;
#pragma unroll
            for (int j = 0; j < 2; j++) {
                const int seg = seg0 + j;
                const int kidx = kbase + (c + 1) * 64 + r;
                const bool ok = (kidx >= 0) && (kidx < SEQ);
                const int kc = ok ? kidx : 0;
                cp16z(sbase + K_OFF + buf * 8192 + SW128((uint32_t)(r * 128 + seg * 16)),
                      qbase + DMODEL + (size_t)kc * qkv_row + seg * 8, ok);
            }
            CP_COMMIT();
            CP_WAIT(1);
        } else {
            CP_WAIT(0);
        }
        __syncthreads();

        const uint32_t qsm = sbase + Q_OFF;
        const uint32_t ksm = sbase + K_OFF + (c & 1) * 8192;
        float sacc[4][4];
#pragma unroll
        for (int j = 0; j < 4; j++)
#pragma unroll
            for (int r = 0; r < 4; r++) sacc[j][r] = 0.f;

        const int a_r = mw + (lane & 15);
        const int a_k = (lane >> 4) << 3;
        const int b_r = nw2 + (lane & 7);
        const int b_k = lane & 8;
#pragma unroll
        for (int kk = 0; kk < 4; kk++) {
            uint32_t ah[4], bh[4][2];
            LDSM_X4(ah[0], ah[1], ah[2], ah[3],
                    qsm + SW128((uint32_t)(a_r * 128 + (kk * 16 + a_k) * 2)));
#pragma unroll
            for (int j = 0; j < 4; j++)
                LDSM_X2(bh[j][0], bh[j][1],
                        ksm + SW128((uint32_t)((b_r + j * 8) * 128 + (kk * 16 + b_k) * 2)));
#pragma unroll
            for (int j = 0; j < 4; j++)
                mma16816(sacc[j], ah, bh[j]);
        }

        // mask + scale -> S f32
#pragma unroll
        for (int j = 0; j < 4; j++) {
            const int colc = nw2 + j * 8 + ec;          // col within chunk
            const int col  = c * 64 + colc;             // col within span
            const int kidx = kbase + col;
#pragma unroll
            for (int half = 0; half < 2; half++) {      // rows er, er+8
                const int row  = mw + er + half * 8;
                const int qidx = q0 + row;
                const int rel0 = kidx - qidx + WHALF;
                const bool ok0 = (rel0 >= 0) && (rel0 <= 2 * WHALF) &&
                                 (kidx >= 0) && (kidx < SEQ);
                const bool ok1 = (rel0 + 1 >= 0) && (rel0 + 1 <= 2 * WHALF) &&
                                 (kidx + 1 >= 0) && (kidx + 1 < SEQ);
                Sf[row * SSTR + col]     = ok0 ? sacc[j][half * 2]     * 0.125f : NEG_INF;
                Sf[row * SSTR + col + 1] = ok1 ? sacc[j][half * 2 + 1] * 0.125f : NEG_INF;
            }
        }
    }

    // ---- V^T staging: VT[d][key], all 5 chunks ----
    {
        const int r = tid >> 2, seg0 = (tid & 3) * 2;   // per chunk: 64 keys x 8 segs
        for (int c = 0; c < 5; c++) {
#pragma unroll
            for (int j = 0; j < 2; j++) {
                const int seg = seg0 + j;
                const int kidx = kbase + c * 64 + r;
                uint4 v = make_uint4(0, 0, 0, 0);
                if (kidx >= 0 && kidx < SEQ)
                    v = *(const uint4*)(qbase + 2 * DMODEL + (size_t)kidx * qkv_row + seg * 8);
                const __half* hv = (const __half*)&v;
                const int key = c * 64 + r;
#pragma unroll
                for (int d = 0; d < 8; d++)
                    VT[(seg * 8 + d) * PSTR + key] = hv[d];
            }
        }
    }
    __syncthreads();   // S + VT complete

    // ---- softmax (f32) -> Ps fp16 ----
    {
        for (int row = wid; row < QT; row += 8) {
            float* Sr = Sf + row * SSTR;
            float m = NEG_INF;
            for (int jj = lane; jj < KSPAN; jj += 32) m = fmaxf(m, Sr[jj]);
#pragma unroll
            for (int off = 16; off; off >>= 1)
                m = fmaxf(m, __shfl_xor_sync(0xffffffffu, m, off));
            float ssum = 0.f;
            for (int jj = lane; jj < KSPAN; jj += 32) {
                float e = expf(Sr[jj] - m);
                Sr[jj] = e;
                ssum += e;
            }
#pragma unroll
            for (int off = 16; off; off >>= 1)
                ssum += __shfl_xor_sync(0xffffffffu, ssum, off);
            float invs = 1.0f / ssum;
            for (int jj = lane; jj < KSPAN; jj += 32)
                Ps[row * PSTR + jj] = __float2half_rn(Sr[jj] * invs);
        }
    }
    __syncthreads();

    // ---- pass B: out = P @ V  (P: [64,320] fp16, V^T: [64,320] fp16) ----
    {
        const int nv = nw2;                 // output d-cols nv..nv+31
        float oacc[4][4];
#pragma unroll
        for (int j = 0; j < 4; j++)
#pragma unroll
            for (int r = 0; r < 4; r++) oacc[j][r] = 0.f;

        const uint32_t psm = sbase + PS_OFF;
        const uint32_t vsm = sbase + VT_OFF;
        const int a_r = mw + (lane & 15);
        const int a_k = (lane >> 4) << 3;
        const int b_r = nv + (lane & 7);
        const int b_k = lane & 8;
#pragma unroll 4
        for (int ks = 0; ks < 20; ks++) {
            uint32_t ah[4], bh[4][2];
            LDSM_X4(ah[0], ah[1], ah[2], ah[3],
                    psm + (uint32_t)(a_r * (PSTR * 2) + (ks * 16 + a_k) * 2));
#pragma unroll
            for (int j = 0; j < 4; j++)
                LDSM_X2(bh[j][0], bh[j][1],
                        vsm + (uint32_t)((b_r + j * 8) * (PSTR * 2) + (ks * 16 + b_k) * 2));
#pragma unroll
            for (int j = 0; j < 4; j++)
                mma16816(oacc[j], ah, bh[j]);
        }

        // write fp16 attention output [B, L, H*hd]
        const int row0 = q0 + mw + er;
#pragma unroll
        for (int j = 0; j < 4; j++) {
            const int d = nv + j * 8 + ec;
            *(__half2*)(ath + (size_t)(b * SEQ + row0) * DMODEL + h * HDIM + d) =
                __floats2half2_rn(oacc[j][0], oacc[j][1]);
            *(__half2*)(ath + (size_t)(b * SEQ + row0 + 8) * DMODEL + h * HDIM + d) =
                __floats2half2_rn(oacc[j][2], oacc[j][3]);
        }
    }
}

// ---------------- launch -----------------------------------------------------
extern "C" void kernel_launch(void* const* d_in, const int* in_sizes, int n_in,
                              void* d_out, int out_size)
{
    const float* x      = (const float*)d_in[0];
    const float* qkv_w  = (const float*)d_in[1];
    const float* qkv_b  = (const float*)d_in[2];
    const float* out_w  = (const float*)d_in[3];
    const float* out_b  = (const float*)d_in[4];
    const float* ln1_g  = (const float*)d_in[5];
    const float* ln1_b  = (const float*)d_in[6];
    const float* ln2_g  = (const float*)d_in[7];
    const float* ln2_b  = (const float*)d_in[8];
    const float* ffn_w1 = (const float*)d_in[9];
    const float* ffn_b1 = (const float*)d_in[10];
    const float* ffn_w2 = (const float*)d_in[11];
    const float* ffn_b2 = (const float*)d_in[12];
    float* out = (float*)d_out;

    float* x1;
    cudaGetSymbolAddress((void**)&x1, g_x1);

    __half *qkvh, *hh, *atth, *h2h, *ffh;
    cudaGetSymbolAddress((void**)&qkvh, g_qkv);
    cudaGetSymbolAddress((void**)&hh,   g_h);
    cudaGetSymbolAddress((void**)&atth, g_att);
    cudaGetSymbolAddress((void**)&h2h,  g_h2);
    cudaGetSymbolAddress((void**)&ffh,  g_ffn);

    __half *wq, *wo, *w1, *w2;
    cudaGetSymbolAddress((void**)&wq, g_wqkv);
    cudaGetSymbolAddress((void**)&wo, g_wout);
    cudaGetSymbolAddress((void**)&w1, g_wf1);
    cudaGetSymbolAddress((void**)&w2, g_wf2);

    cudaFuncSetAttribute(attn_kernel, cudaFuncAttributeMaxDynamicSharedMemorySize, ATT_SMEM);
    cudaFuncSetAttribute(hmma_gemm<1>, cudaFuncAttributeMaxDynamicSharedMemorySize, GEMM_SMEM);
    cudaFuncSetAttribute(hmma_gemm<2>, cudaFuncAttributeMaxDynamicSharedMemorySize, GEMM_SMEM);
    cudaFuncSetAttribute(hmma_gemm<3>, cudaFuncAttributeMaxDynamicSharedMemorySize, GEMM_SMEM);

    // 0) weight transpose -> fp16 [N,K]
    transpose_fp16<<<dim3(3*DMODEL/32, DMODEL/32), 256>>>(qkv_w, wq, DMODEL, 3*DMODEL);
    transpose_fp16<<<dim3(DMODEL/32,   DMODEL/32), 256>>>(out_w, wo, DMODEL, DMODEL);
    transpose_fp16<<<dim3(2*DMODEL/32, DMODEL/32), 256>>>(ffn_w1, w1, DMODEL, 2*DMODEL);
    transpose_fp16<<<dim3(DMODEL/32, 2*DMODEL/32), 256>>>(ffn_w2, w2, 2*DMODEL, DMODEL);

    // 1) LN1(x) -> h (fp16)
    ln_kernel<<<ROWS, 256>>>(x, ln1_g, ln1_b, hh);
    // 2) qkv = h @ qkv_w + qkv_b  (fp16)
    hmma_gemm<3><<<dim3(3*DMODEL/128, ROWS/128), 256, GEMM_SMEM>>>(
        hh, wq, qkv_b, nullptr, nullptr, qkvh, ROWS, 3*DMODEL, DMODEL);
    // 3) HMMA windowed attention -> att (fp16)
    attn_kernel<<<dim3(SEQ/QT, NHEADS, BATCH), 256, ATT_SMEM>>>(qkvh, atth);
    // 4) x1 = x + att @ out_w + out_b (f32)
    hmma_gemm<1><<<dim3(DMODEL/128, ROWS/128), 256, GEMM_SMEM>>>(
        atth, wo, out_b, x, x1, nullptr, ROWS, DMODEL, DMODEL);
    // 5) LN2(x1) -> h2 (fp16)
    ln_kernel<<<ROWS, 256>>>(x1, ln2_g, ln2_b, h2h);
    // 6) ffn = gelu(h2 @ ffn_w1 + ffn_b1)  (fp16)
    hmma_gemm<2><<<dim3(2*DMODEL/128, ROWS/128), 256, GEMM_SMEM>>>(
        h2h, w1, ffn_b1, nullptr, nullptr, ffh, ROWS, 2*DMODEL, DMODEL);
    // 7) out = x1 + ffn @ ffn_w2 + ffn_b2 (f32)
    hmma_gemm<1><<<dim3(DMODEL/128, ROWS/128), 256, GEMM_SMEM>>>(
        ffh, w2, ffn_b2, x1, out, nullptr, ROWS, DMODEL, 2*DMODEL);
}

// round 7
// speedup vs baseline: 4.6455x; 1.0704x over previous
#include <cuda_runtime.h>
#include <cuda_fp16.h>
#include <math.h>
#include <stdint.h>

// ---------------- problem constants ----------------
#define BATCH 2
#define SEQ   2048
#define DMODEL 1024
#define NHEADS 16
#define HDIM  64
#define ROWS  (BATCH*SEQ)          // 4096
#define WHALF 128
#define LN_EPS 1e-5f

// ---------------- scratch (device globals) ----------
__device__ float  g_x1 [ROWS * DMODEL];          // f32 residual / LN2 input
__device__ __half g_qkv[ROWS * 3 * DMODEL];      // fp16 qkv
__device__ __half g_h  [ROWS * DMODEL];
__device__ __half g_att[ROWS * DMODEL];
__device__ __half g_h2 [ROWS * DMODEL];
__device__ __half g_ffn[ROWS * 2 * DMODEL];

// transposed fp16 weights: [N, K] row-major
__device__ __half g_wqkv[3*DMODEL*DMODEL];
__device__ __half g_wout[DMODEL*DMODEL];
__device__ __half g_wf1 [2*DMODEL*DMODEL];
__device__ __half g_wf2 [2*DMODEL*DMODEL];

// ---------------- helpers ----------------------------------------------------
__device__ __forceinline__ uint32_t smem_u32(const void* p) {
    uint32_t a;
    asm("{ .reg .u64 t; cvta.to.shared.u64 t, %1; cvt.u32.u64 %0, t; }"
        : "=r"(a) : "l"(p));
    return a;
}
#define SW128(off) ((off) ^ (((off) >> 3) & 0x70))

__device__ __forceinline__ void cp16(uint32_t smem, const void* g) {
    asm volatile("cp.async.cg.shared.global [%0], [%1], 16;"
        :: "r"(smem), "l"(g) : "memory");
}
__device__ __forceinline__ void cp16z(uint32_t smem, const void* g, bool valid) {
    int sz = valid ? 16 : 0;
    asm volatile("cp.async.cg.shared.global [%0], [%1], 16, %2;"
        :: "r"(smem), "l"(g), "r"(sz) : "memory");
}
#define CP_COMMIT() asm volatile("cp.async.commit_group;" ::: "memory")
#define CP_WAIT(n)  asm volatile("cp.async.wait_group %0;" :: "n"(n) : "memory")

#define LDSM_X4(r0,r1,r2,r3,addr) \
    asm volatile("ldmatrix.sync.aligned.m8n8.x4.shared.b16 {%0,%1,%2,%3}, [%4];" \
        : "=r"(r0), "=r"(r1), "=r"(r2), "=r"(r3) : "r"(addr))
#define LDSM_X2(r0,r1,addr) \
    asm volatile("ldmatrix.sync.aligned.m8n8.x2.shared.b16 {%0,%1}, [%2];" \
        : "=r"(r0), "=r"(r1) : "r"(addr))
#define LDSM_X2_T(r0,r1,addr) \
    asm volatile("ldmatrix.sync.aligned.m8n8.x2.trans.shared.b16 {%0,%1}, [%2];" \
        : "=r"(r0), "=r"(r1) : "r"(addr))

__device__ __forceinline__ void mma16816(float* d, const uint32_t* a, const uint32_t* b) {
    asm volatile(
        "mma.sync.aligned.m16n8k16.row.col.f32.f16.f16.f32 "
        "{%0,%1,%2,%3}, {%4,%5,%6,%7}, {%8,%9}, {%0,%1,%2,%3};"
        : "+f"(d[0]), "+f"(d[1]), "+f"(d[2]), "+f"(d[3])
        : "r"(a[0]), "r"(a[1]), "r"(a[2]), "r"(a[3]), "r"(b[0]), "r"(b[1]));
}

// ---------------- transpose weights: w [K,N] f32 -> t [N,K] fp16 -------------
__global__ __launch_bounds__(256) void transpose_fp16(
    const float* __restrict__ w, __half* __restrict__ t, int K, int N)
{
    __shared__ float tb[32][33];
    const int n0 = blockIdx.x * 32, k0 = blockIdx.y * 32;
    const int c = threadIdx.x & 31, r = threadIdx.x >> 5;
#pragma unroll
    for (int i = 0; i < 32; i += 8)
        tb[r + i][c] = w[(size_t)(k0 + r + i) * N + n0 + c];
    __syncthreads();
#pragma unroll
    for (int i = 0; i < 32; i += 8)
        t[(size_t)(n0 + r + i) * K + k0 + c] = __float2half_rn(tb[c][r + i]);
}

// ---------------- HMMA GEMM --------------------------------------------------
// C[M,N] = A[M,K] @ B^T ; A fp16 [M,K], B fp16 [N,K].
// 128x128 CTA tile, 8 warps of 64x32, K-step 64, 3-stage cp.async, 2 CTAs/SM.
// EPI 1: f32 = acc+bias+res ; 2: fp16 = gelu(acc+bias) ; 3: fp16 = acc+bias
#define OFF_A 0
#define OFF_B 16384
#define STAGE_BYTES 32768
#define NSTAGE 3
#define GEMM_SMEM (NSTAGE*STAGE_BYTES)   // 98304

template<int EPI>
__global__ __launch_bounds__(256, 2) void hmma_gemm(
    const __half* __restrict__ A, const __half* __restrict__ B,
    const float* __restrict__ bias, const float* __restrict__ res,
    float* __restrict__ Cf, __half* __restrict__ Ch,
    int M, int N, int K)
{
    extern __shared__ char smc[];
    const uint32_t sbase = smem_u32(smc);
    const int tid = threadIdx.x, wid = tid >> 5, lane = tid & 31;
    const int m0 = blockIdx.y * 128, n0 = blockIdx.x * 128;
    const int mw = (wid >> 2) * 64;
    const int nw = (wid & 3) * 32;

    float acc[4][4][4];
#pragma unroll
    for (int i = 0; i < 4; i++)
#pragma unroll
        for (int j = 0; j < 4; j++)
#pragma unroll
            for (int r = 0; r < 4; r++) acc[i][j][r] = 0.f;

    const int S = K >> 6;
    const int lrow = tid >> 1;
    const int lsq  = (tid & 1) * 4;

    auto load_stage = [&](int buf, int koff) {
        const uint32_t st = sbase + buf * STAGE_BYTES;
        const __half* gA = A + (size_t)(m0 + lrow) * K + koff;
        const __half* gB = B + (size_t)(n0 + lrow) * K + koff;
#pragma unroll
        for (int j = 0; j < 4; j++) {
            const int seg = lsq + j;
            const uint32_t so = SW128((uint32_t)(lrow * 128 + seg * 16));
            cp16(st + OFF_A + so, gA + seg * 8);
            cp16(st + OFF_B + so, gB + seg * 8);
        }
    };

    const int a_r = mw + (lane & 15);
    const int a_k = (lane >> 4) << 3;
    const int b_r = nw + (lane & 7);
    const int b_k = lane & 8;

    // prologue: stages 0,1
    load_stage(0, 0);
    CP_COMMIT();
    load_stage(1, 1 << 6);
    CP_COMMIT();

    int cbuf = 0, lbuf = 2;
    for (int s = 0; s < S; s++) {
        CP_WAIT(1);                 // stage s complete
        __syncthreads();            // all warps past stage s-1 compute
        if (s + NSTAGE - 1 < S) load_stage(lbuf, (s + NSTAGE - 1) << 6);
        CP_COMMIT();

        const uint32_t st = sbase + cbuf * STAGE_BYTES;
#pragma unroll
        for (int kk = 0; kk < 4; kk++) {
            uint32_t ah[4][4], bh[4][2];
#pragma unroll
            for (int i = 0; i < 4; i++) {
                uint32_t ad = st + OFF_A +
                    SW128((uint32_t)((a_r + i * 16) * 128 + (kk * 16 + a_k) * 2));
                LDSM_X4(ah[i][0], ah[i][1], ah[i][2], ah[i][3], ad);
            }
#pragma unroll
            for (int j = 0; j < 4; j++) {
                uint32_t off = SW128((uint32_t)((b_r + j * 8) * 128 + (kk * 16 + b_k) * 2));
                LDSM_X2(bh[j][0], bh[j][1], st + OFF_B + off);
            }
#pragma unroll
            for (int i = 0; i < 4; i++)
#pragma unroll
                for (int j = 0; j < 4; j++)
                    mma16816(acc[i][j], ah[i], bh[j]);
        }
        cbuf = (cbuf == NSTAGE - 1) ? 0 : cbuf + 1;
        lbuf = (lbuf == NSTAGE - 1) ? 0 : lbuf + 1;
    }

    // ---------------- epilogue ----------------
    const int er = lane >> 2;
    const int ec = 2 * (lane & 3);
#pragma unroll
    for (int i = 0; i < 4; i++) {
        const int row0 = m0 + mw + i * 16 + er;
        const int row1 = row0 + 8;
#pragma unroll
        for (int j = 0; j < 4; j++) {
            const int col = n0 + nw + j * 8 + ec;
            const float b0 = bias[col], b1 = bias[col + 1];
            float v0 = acc[i][j][0] + b0;
            float v1 = acc[i][j][1] + b1;
            float v2 = acc[i][j][2] + b0;
            float v3 = acc[i][j][3] + b1;
            if (EPI == 1) {
                const float2 r0 = *(const float2*)(res + (size_t)row0 * N + col);
                const float2 r1 = *(const float2*)(res + (size_t)row1 * N + col);
                v0 += r0.x; v1 += r0.y; v2 += r1.x; v3 += r1.y;
                *(float2*)(Cf + (size_t)row0 * N + col) = make_float2(v0, v1);
                *(float2*)(Cf + (size_t)row1 * N + col) = make_float2(v2, v3);
            }
            if (EPI == 2) {
                v0 = 0.5f * v0 * (1.0f + erff(v0 * 0.70710678118654752f));
                v1 = 0.5f * v1 * (1.0f + erff(v1 * 0.70710678118654752f));
                v2 = 0.5f * v2 * (1.0f + erff(v2 * 0.70710678118654752f));
                v3 = 0.5f * v3 * (1.0f + erff(v3 * 0.70710678118654752f));
                *(__half2*)(Ch + (size_t)row0 * N + col) = __floats2half2_rn(v0, v1);
                *(__half2*)(Ch + (size_t)row1 * N + col) = __floats2half2_rn(v2, v3);
            }
            if (EPI == 3) {
                *(__half2*)(Ch + (size_t)row0 * N + col) = __floats2half2_rn(v0, v1);
                *(__half2*)(Ch + (size_t)row1 * N + col) = __floats2half2_rn(v2, v3);
            }
        }
    }
}

// ---------------- LayerNorm (writes fp16) ------------------------------------
__global__ __launch_bounds__(256) void ln_kernel(
    const float* __restrict__ x, const float* __restrict__ g,
    const float* __restrict__ b, __half* __restrict__ oh)
{
    const int row = blockIdx.x;
    const float* xr = x + (size_t)row * DMODEL;
    const int tid = threadIdx.x;

    float v[4];
    float s = 0.f, ss = 0.f;
#pragma unroll
    for (int i = 0; i < 4; i++) {
        v[i] = xr[tid + i * 256];
        s += v[i];
        ss += v[i] * v[i];
    }
#pragma unroll
    for (int off = 16; off; off >>= 1) {
        s  += __shfl_xor_sync(0xffffffffu, s, off);
        ss += __shfl_xor_sync(0xffffffffu, ss, off);
    }
    __shared__ float rs[8], rss[8];
    const int warp = tid >> 5, lane = tid & 31;
    if (lane == 0) { rs[warp] = s; rss[warp] = ss; }
    __syncthreads();
    __shared__ float s_mu, s_inv;
    if (tid == 0) {
        float S = 0.f, SS = 0.f;
#pragma unroll
        for (int w = 0; w < 8; w++) { S += rs[w]; SS += rss[w]; }
        float mu = S * (1.0f / DMODEL);
        float var = SS * (1.0f / DMODEL) - mu * mu;
        s_mu = mu;
        s_inv = rsqrtf(var + LN_EPS);
    }
    __syncthreads();
    const float mu = s_mu, inv = s_inv;
#pragma unroll
    for (int i = 0; i < 4; i++) {
        int c = tid + i * 256;
        float o = (v[i] - mu) * inv * g[c] + b[c];
        oh[(size_t)row * DMODEL + c] = __float2half_rn(o);
    }
}

// ---------------- HMMA windowed attention ------------------------------------
// Block = (b, h, 64 queries). Key span 320 = 5 chunks of 64.
// V staged row-major (swizzled); P@V uses ldmatrix.trans — no V^T staging.
#define QT 64
#define KSPAN 320
#define SSTR 321                    // f32 score row stride
#define PSTR 328                    // fp16 P row stride (656B: conflict-free)
#define S_OFF  0
#define PS_OFF 82176                // 64*321*4
#define Q_OFF  124160               // +64*328*2
#define K_OFF  132352               // +8192
#define V_OFF  148736               // +2*8192
#define ATT_SMEM 189696             // +5*8192

__global__ __launch_bounds__(256, 1) void attn_kernel(
    const __half* __restrict__ qkv, __half* __restrict__ ath)
{
    extern __shared__ char smc[];
    const uint32_t sbase = smem_u32(smc);
    float*  Sf = (float*)(smc + S_OFF);
    __half* Ps = (__half*)(smc + PS_OFF);

    const int q0 = blockIdx.x * QT;
    const int h  = blockIdx.y;
    const int b  = blockIdx.z;
    const int tid = threadIdx.x, wid = tid >> 5, lane = tid & 31;
    const int kbase = q0 - WHALF;
    const float NEG_INF = __int_as_float(0xff800000);

    const size_t qkv_row = 3 * DMODEL;
    const __half* qbase = qkv + (size_t)(b * SEQ) * qkv_row + h * HDIM;

    const int mw  = (wid & 3) * 16;
    const int nw2 = (wid >> 2) * 32;
    const int er = lane >> 2, ec = 2 * (lane & 3);

    const int r = tid >> 2, seg0 = (tid & 3) * 2;   // loader: 64 rows x 8 segs

    // ---- prologue: g0 = {Q, K0}, g1 = {V all 5 chunks} ----
    {
#pragma unroll
        for (int j = 0; j < 2; j++) {
            const int seg = seg0 + j;
            cp16(sbase + Q_OFF + SW128((uint32_t)(r * 128 + seg * 16)),
                 qbase + (size_t)(q0 + r) * qkv_row + seg * 8);
            const int kidx = kbase + r;
            const bool ok = (kidx >= 0) && (kidx < SEQ);
            const int kc = ok ? kidx : 0;
            cp16z(sbase + K_OFF + SW128((uint32_t)(r * 128 + seg * 16)),
                  qbase + DMODEL + (size_t)kc * qkv_row + seg * 8, ok);
        }
        CP_COMMIT();
        for (int c = 0; c < 5; c++) {
#pragma unroll
            for (int j = 0; j < 2; j++) {
                const int seg = seg0 + j;
                const int kidx = kbase + c * 64 + r;
                const bool ok = (kidx >= 0) && (kidx < SEQ);
                const int kc = ok ? kidx : 0;
                cp16z(sbase + V_OFF + c * 8192 + SW128((uint32_t)(r * 128 + seg * 16)),
                      qbase + 2 * DMODEL + (size_t)kc * qkv_row + seg * 8, ok);
            }
        }
        CP_COMMIT();
    }

    // ---- pass A: scores (5 chunks, K double-buffered; V overlapped) ----
    for (int c = 0; c < 5; c++) {
        __syncthreads();            // guard K buffer reuse
        if (c + 1 < 5) {
            const int buf = (c + 1) & 1;
#pragma unroll
            for (int j = 0; j < 2; j++) {
                const int seg = seg0 + j;
                const int kidx = kbase + (c + 1) * 64 + r;
                const bool ok = (kidx >= 0) && (kidx < SEQ);
                const int kc = ok ? kidx : 0;
                cp16z(sbase + K_OFF + buf * 8192 + SW128((uint32_t)(r * 128 + seg * 16)),
                      qbase + DMODEL + (size_t)kc * qkv_row + seg * 8, ok);
            }
        }
        CP_COMMIT();
        if (c == 0) { CP_WAIT(2); } else { CP_WAIT(1); }
        __syncthreads();

        const uint32_t qsm = sbase + Q_OFF;
        const uint32_t ksm = sbase + K_OFF + (c & 1) * 8192;
        float sacc[4][4];
#pragma unroll
        for (int j = 0; j < 4; j++)
#pragma unroll
            for (int rr = 0; rr < 4; rr++) sacc[j][rr] = 0.f;

        const int a_r = mw + (lane & 15);
        const int a_k = (lane >> 4) << 3;
        const int b_r = nw2 + (lane & 7);
        const int b_k = lane & 8;
#pragma unroll
        for (int kk = 0; kk < 4; kk++) {
            uint32_t ah[4], bh[4][2];
            LDSM_X4(ah[0], ah[1], ah[2], ah[3],
                    qsm + SW128((uint32_t)(a_r * 128 + (kk * 16 + a_k) * 2)));
#pragma unroll
            for (int j = 0; j < 4; j++)
                LDSM_X2(bh[j][0], bh[j][1],
                        ksm + SW128((uint32_t)((b_r + j * 8) * 128 + (kk * 16 + b_k) * 2)));
#pragma unroll
            for (int j = 0; j < 4; j++)
                mma16816(sacc[j], ah, bh[j]);
        }

        // mask + scale -> S f32
#pragma unroll
        for (int j = 0; j < 4; j++) {
            const int colc = nw2 + j * 8 + ec;
            const int col  = c * 64 + colc;
            const int kidx = kbase + col;
#pragma unroll
            for (int half = 0; half < 2; half++) {
                const int row  = mw + er + half * 8;
                const int qidx = q0 + row;
                const int rel0 = kidx - qidx + WHALF;
                const bool ok0 = (rel0 >= 0) && (rel0 <= 2 * WHALF) &&
                                 (kidx >= 0) && (kidx < SEQ);
                const bool ok1 = (rel0 + 1 >= 0) && (rel0 + 1 <= 2 * WHALF) &&
                                 (kidx + 1 >= 0) && (kidx + 1 < SEQ);
                Sf[row * SSTR + col]     = ok0 ? sacc[j][half * 2]     * 0.125f : NEG_INF;
                Sf[row * SSTR + col + 1] = ok1 ? sacc[j][half * 2 + 1] * 0.125f : NEG_INF;
            }
        }
    }
    __syncthreads();   // all scores written

    // ---- softmax (f32) -> Ps fp16 ----
    {
        for (int row = wid; row < QT; row += 8) {
            float* Sr = Sf + row * SSTR;
            float m = NEG_INF;
            for (int jj = lane; jj < KSPAN; jj += 32) m = fmaxf(m, Sr[jj]);
#pragma unroll
            for (int off = 16; off; off >>= 1)
                m = fmaxf(m, __shfl_xor_sync(0xffffffffu, m, off));
            float ssum = 0.f;
            for (int jj = lane; jj < KSPAN; jj += 32) {
                float e = expf(Sr[jj] - m);
                Sr[jj] = e;
                ssum += e;
            }
#pragma unroll
            for (int off = 16; off; off >>= 1)
                ssum += __shfl_xor_sync(0xffffffffu, ssum, off);
            float invs = 1.0f / ssum;
            for (int jj = lane; jj < KSPAN; jj += 32)
                Ps[row * PSTR + jj] = __float2half_rn(Sr[jj] * invs);
        }
    }
    __syncthreads();

    // ---- pass B: out = P @ V (A=Ps, B=V via ldmatrix.trans) ----
    {
        const int nv = nw2;
        float oacc[4][4];
#pragma unroll
        for (int j = 0; j < 4; j++)
#pragma unroll
            for (int rr = 0; rr < 4; rr++) oacc[j][rr] = 0.f;

        const uint32_t psm = sbase + PS_OFF;
        const uint32_t vsm = sbase + V_OFF;
        const int a_r = mw + (lane & 15);
        const int a_k = (lane >> 4) << 3;
        const int v_key = lane & 15;     // trans B: lane -> key row
#pragma unroll 4
        for (int ks = 0; ks < 20; ks++) {
            const int chunk = ks >> 2;
            const int lk = (ks & 3) * 16 + v_key;
            uint32_t ah[4], bh[4][2];
            LDSM_X4(ah[0], ah[1], ah[2], ah[3],
                    psm + (uint32_t)(a_r * (PSTR * 2) + (ks * 16 + a_k) * 2));
#pragma unroll
            for (int j = 0; j < 4; j++) {
                const int db = nv + j * 8;
                LDSM_X2_T(bh[j][0], bh[j][1],
                          vsm + chunk * 8192 + SW128((uint32_t)(lk * 128 + db * 2)));
            }
#pragma unroll
            for (int j = 0; j < 4; j++)
                mma16816(oacc[j], ah, bh[j]);
        }

        const int row0 = q0 + mw + er;
#pragma unroll
        for (int j = 0; j < 4; j++) {
            const int d = nv + j * 8 + ec;
            *(__half2*)(ath + (size_t)(b * SEQ + row0) * DMODEL + h * HDIM + d) =
                __floats2half2_rn(oacc[j][0], oacc[j][1]);
            *(__half2*)(ath + (size_t)(b * SEQ + row0 + 8) * DMODEL + h * HDIM + d) =
                __floats2half2_rn(oacc[j][2], oacc[j][3]);
        }
    }
}

// ---------------- launch -----------------------------------------------------
extern "C" void kernel_launch(void* const* d_in, const int* in_sizes, int n_in,
                              void* d_out, int out_size)
{
    const float* x      = (const float*)d_in[0];
    const float* qkv_w  = (const float*)d_in[1];
    const float* qkv_b  = (const float*)d_in[2];
    const float* out_w  = (const float*)d_in[3];
    const float* out_b  = (const float*)d_in[4];
    const float* ln1_g  = (const float*)d_in[5];
    const float* ln1_b  = (const float*)d_in[6];
    const float* ln2_g  = (const float*)d_in[7];
    const float* ln2_b  = (const float*)d_in[8];
    const float* ffn_w1 = (const float*)d_in[9];
    const float* ffn_b1 = (const float*)d_in[10];
    const float* ffn_w2 = (const float*)d_in[11];
    const float* ffn_b2 = (const float*)d_in[12];
    float* out = (float*)d_out;

    float* x1;
    cudaGetSymbolAddress((void**)&x1, g_x1);

    __half *qkvh, *hh, *atth, *h2h, *ffh;
    cudaGetSymbolAddress((void**)&qkvh, g_qkv);
    cudaGetSymbolAddress((void**)&hh,   g_h);
    cudaGetSymbolAddress((void**)&atth, g_att);
    cudaGetSymbolAddress((void**)&h2h,  g_h2);
    cudaGetSymbolAddress((void**)&ffh,  g_ffn);

    __half *wq, *wo, *w1, *w2;
    cudaGetSymbolAddress((void**)&wq, g_wqkv);
    cudaGetSymbolAddress((void**)&wo, g_wout);
    cudaGetSymbolAddress((void**)&w1, g_wf1);
    cudaGetSymbolAddress((void**)&w2, g_wf2);

    cudaFuncSetAttribute(attn_kernel, cudaFuncAttributeMaxDynamicSharedMemorySize, ATT_SMEM);
    cudaFuncSetAttribute(hmma_gemm<1>, cudaFuncAttributeMaxDynamicSharedMemorySize, GEMM_SMEM);
    cudaFuncSetAttribute(hmma_gemm<2>, cudaFuncAttributeMaxDynamicSharedMemorySize, GEMM_SMEM);
    cudaFuncSetAttribute(hmma_gemm<3>, cudaFuncAttributeMaxDynamicSharedMemorySize, GEMM_SMEM);

    // 0) weight transpose -> fp16 [N,K]
    transpose_fp16<<<dim3(3*DMODEL/32, DMODEL/32), 256>>>(qkv_w, wq, DMODEL, 3*DMODEL);
    transpose_fp16<<<dim3(DMODEL/32,   DMODEL/32), 256>>>(out_w, wo, DMODEL, DMODEL);
    transpose_fp16<<<dim3(2*DMODEL/32, DMODEL/32), 256>>>(ffn_w1, w1, DMODEL, 2*DMODEL);
    transpose_fp16<<<dim3(DMODEL/32, 2*DMODEL/32), 256>>>(ffn_w2, w2, 2*DMODEL, DMODEL);

    // 1) LN1(x) -> h (fp16)
    ln_kernel<<<ROWS, 256>>>(x, ln1_g, ln1_b, hh);
    // 2) qkv = h @ qkv_w + qkv_b  (fp16)
    hmma_gemm<3><<<dim3(3*DMODEL/128, ROWS/128), 256, GEMM_SMEM>>>(
        hh, wq, qkv_b, nullptr, nullptr, qkvh, ROWS, 3*DMODEL, DMODEL);
    // 3) HMMA windowed attention -> att (fp16)
    attn_kernel<<<dim3(SEQ/QT, NHEADS, BATCH), 256, ATT_SMEM>>>(qkvh, atth);
    // 4) x1 = x + att @ out_w + out_b (f32)
    hmma_gemm<1><<<dim3(DMODEL/128, ROWS/128), 256, GEMM_SMEM>>>(
        atth, wo, out_b, x, x1, nullptr, ROWS, DMODEL, DMODEL);
    // 5) LN2(x1) -> h2 (fp16)
    ln_kernel<<<ROWS, 256>>>(x1, ln2_g, ln2_b, h2h);
    // 6) ffn = gelu(h2 @ ffn_w1 + ffn_b1)  (fp16)
    hmma_gemm<2><<<dim3(2*DMODEL/128, ROWS/128), 256, GEMM_SMEM>>>(
        h2h, w1, ffn_b1, nullptr, nullptr, ffh, ROWS, 2*DMODEL, DMODEL);
    // 7) out = x1 + ffn @ ffn_w2 + ffn_b2 (f32)
    hmma_gemm<1><<<dim3(DMODEL/128, ROWS/128), 256, GEMM_SMEM>>>(
        ffh, w2, ffn_b2, x1, out, nullptr, ROWS, DMODEL, 2*DMODEL);
}